// round 8
// baseline (speedup 1.0000x reference)
#include <cuda_runtime.h>
#include <cuda_bf16.h>
#include <math.h>
#include <stdint.h>

// Problem constants
#define NB   32
#define NPG0 128
#define NE   8192
#define EPG  (NE/NB)      // 256 edges per graph (contiguous slots, valid-flagged)
#define CIN0 64
#define ED   32
#define HH   128
#define NDB  34           // 32 edge-dim slices + bias slice + root slice
#define K1   64
#define K2   32
#define K3   16
#define NN0  (NB*NPG0)    // 4096
#define NSPLIT 3

// ---------------- scratch ----------------
__device__ __nv_bfloat16 g_Ab[NN0 * NSPLIT * HH];
__device__ __nv_bfloat16 g_Bb[(NDB * HH) * NSPLIT * HH];
__device__ float g_h[NN0 * HH];
__device__ float g_h2[NN0 * HH];
__device__ int   g_src[NE], g_dst[NE], g_valid[NE];
__device__ float g_partial[64 * 256];

// ---------------- helpers ----------------
__device__ __forceinline__ void split2(float x, __nv_bfloat16& h1, __nv_bfloat16& h2) {
    h1 = __float2bfloat16(x);
    h2 = __float2bfloat16(x - __bfloat162float(h1));
}
__device__ __forceinline__ uint32_t smem_u32(const void* p) {
    return (uint32_t)__cvta_generic_to_shared(p);
}
__device__ __forceinline__ void cp_async16(uint32_t saddr, const void* gaddr) {
    asm volatile("cp.async.cg.shared.global [%0], [%1], 16;" :: "r"(saddr), "l"(gaddr));
}
__device__ __forceinline__ void ldsm4(uint32_t& r0, uint32_t& r1, uint32_t& r2, uint32_t& r3,
                                      uint32_t addr) {
    asm volatile("ldmatrix.sync.aligned.m8n8.x4.shared.b16 {%0,%1,%2,%3}, [%4];"
                 : "=r"(r0), "=r"(r1), "=r"(r2), "=r"(r3) : "r"(addr));
}
__device__ __forceinline__ void mma16816(float* c, const uint32_t* a, const uint32_t* b) {
    asm volatile("mma.sync.aligned.m16n8k16.row.col.f32.bf16.bf16.f32 "
                 "{%0,%1,%2,%3}, {%4,%5,%6,%7}, {%8,%9}, {%0,%1,%2,%3};"
                 : "+f"(c[0]), "+f"(c[1]), "+f"(c[2]), "+f"(c[3])
                 : "r"(a[0]), "r"(a[1]), "r"(a[2]), "r"(a[3]), "r"(b[0]), "r"(b[1]));
}

// ---------------- split prep ----------------
// Ab[r, j*cin+k], blocks [h1, h1, h2]
__global__ void split_A_k(const float* __restrict__ A, __nv_bfloat16* __restrict__ Ab,
                          int n, int cin) {
    int i = blockIdx.x * blockDim.x + threadIdx.x;
    if (i >= n * cin) return;
    int r = i / cin, k = i - r * cin;
    __nv_bfloat16 h1, h2;
    split2(A[i], h1, h2);
    __nv_bfloat16* row = Ab + (size_t)r * NSPLIT * cin + k;
    row[0] = h1; row[cin] = h1; row[2 * cin] = h2;
}

// BbT[t, j*cin+k], blocks [b1, b2, b1]; t = d*128+o
__global__ void split_B_k(const float* __restrict__ W, const float* __restrict__ bvec,
                          const float* __restrict__ root, __nv_bfloat16* __restrict__ Bb,
                          int cin) {
    int i = blockIdx.x * blockDim.x + threadIdx.x;
    if (i >= NDB * HH * cin) return;
    int t = i / cin, k = i - t * cin;
    int d = t >> 7, o = t & 127;
    float w;
    if (d < ED)       w = W[(size_t)(d * cin + k) * HH + o];
    else if (d == ED) w = bvec[(size_t)k * HH + o];
    else              w = root[(size_t)k * HH + o];
    __nv_bfloat16 b1, b2;
    split2(w, b1, b2);
    __nv_bfloat16* row = Bb + (size_t)t * NSPLIT * cin + k;
    row[0] = b1; row[cin] = b2; row[2 * cin] = b1;
}

// h2[v, o] = bias[o]  (per-node conv bias; GEMM epilogue atomically accumulates onto it)
__global__ void init_h2_k(const float* __restrict__ bias, float* __restrict__ h2) {
    h2[(size_t)blockIdx.x * HH + threadIdx.x] = bias[threadIdx.x];
}

// ---------------- fused GEMM + edge-scatter ----------------
// Block (dblk, yblk): computes tile T[128 rows, 128 cols] of X_split @ B_split for
// d-slice dblk. dblk<33: T -> smem, then scatter per edge:
//   h2[dst] += coef * T[src_local]   (coef = ea[e,dblk] for dblk<32; 1 for bias slice 32)
// dblk==33 (root): h2[row] += T[row] directly (atomic; h2 pre-init to bias).
#define BK   64
#define SROW 72                // 64+8 bf16 per row slot (144B): conflict-free ldsm
#define STG  (128 * SROW)      // elems per matrix per stage
#define GEMM_SMEM (3 * 2 * STG * 2)   // 110592 bytes (>= 64KB ytile reuse)

__global__ __launch_bounds__(512, 2)
void gemm_fused_k(const __nv_bfloat16* __restrict__ Ab, const __nv_bfloat16* __restrict__ Bb,
                  const float* __restrict__ ea,
                  const int* __restrict__ src, const int* __restrict__ dst,
                  const int* __restrict__ valid,
                  float* __restrict__ h2, int Kp, int npg) {
    extern __shared__ __nv_bfloat16 sm[];
    const int tid = threadIdx.x;
    const int lane = tid & 31;
    const int wid = tid >> 5;
    const int warp_m = wid & 3;     // 0..3
    const int warp_n = wid >> 2;    // 0..3
    const int dblk = blockIdx.x;    // 0..33
    const int mbase = blockIdx.y * 128;
    const int nbase = dblk * 128;
    const int NC = Kp >> 6;

    float acc[2][4][4];
#pragma unroll
    for (int i = 0; i < 2; i++)
#pragma unroll
        for (int j = 0; j < 4; j++)
#pragma unroll
            for (int q = 0; q < 4; q++) acc[i][j][q] = 0.f;

    auto prefetch = [&](int cIdx, int s) {
        const int kc = cIdx * BK;
        __nv_bfloat16* base = sm + s * 2 * STG;
#pragma unroll
        for (int u = 0; u < 4; u++) {
            int q = tid + u * 512;           // 0..2047
            int isB = q >> 10;
            int qq = q & 1023;
            int r = qq >> 3, ch = qq & 7;
            const __nv_bfloat16* g = isB
                ? (Bb + (size_t)(nbase + r) * Kp + kc + ch * 8)
                : (Ab + (size_t)(mbase + r) * Kp + kc + ch * 8);
            cp_async16(smem_u32(base + isB * STG + r * SROW + ch * 8), g);
        }
        asm volatile("cp.async.commit_group;" ::: "memory");
    };

    prefetch(0, 0);
    if (NC > 1) prefetch(1, 1);

    for (int c = 0; c < NC; c++) {
        if (c + 1 < NC) asm volatile("cp.async.wait_group 1;" ::: "memory");
        else            asm volatile("cp.async.wait_group 0;" ::: "memory");
        __syncthreads();
        if (c + 2 < NC) prefetch(c + 2, (c + 2) % 3);

        const int s = c % 3;
        const uint32_t a_base = smem_u32(sm + s * 2 * STG);
        const uint32_t b_base = a_base + STG * 2;   // bytes

        uint32_t af[2][2][4];
        uint32_t bf[2][4][2];

        auto load_frags = [&](int kk, int buf) {
            int acol = kk * 16 + (lane >> 4) * 8;
#pragma unroll
            for (int i = 0; i < 2; i++) {
                int arow = warp_m * 32 + i * 16 + (lane & 15);
                ldsm4(af[buf][i][0], af[buf][i][1], af[buf][i][2], af[buf][i][3],
                      a_base + (uint32_t)(arow * SROW + acol) * 2);
            }
            int m8 = lane >> 3;
            int kcol = kk * 16 + (m8 & 1) * 8;
#pragma unroll
            for (int g = 0; g < 2; g++) {
                int nrow = warp_n * 32 + (2 * g + (m8 >> 1)) * 8 + (lane & 7);
                ldsm4(bf[buf][2 * g][0], bf[buf][2 * g][1],
                      bf[buf][2 * g + 1][0], bf[buf][2 * g + 1][1],
                      b_base + (uint32_t)(nrow * SROW + kcol) * 2);
            }
        };

        load_frags(0, 0);
#pragma unroll
        for (int kk = 0; kk < 4; kk++) {
            int cur = kk & 1;
            if (kk < 3) load_frags(kk + 1, cur ^ 1);
#pragma unroll
            for (int i = 0; i < 2; i++)
#pragma unroll
                for (int j = 0; j < 4; j++)
                    mma16816(acc[i][j], af[cur][i], bf[cur][j]);
        }
    }

    // ---- epilogue ----
    const int gid = lane >> 2, tig = lane & 3;
    if (dblk == 33) {
        // root slice: h2[row] += acc  (h2 pre-initialized to bias)
#pragma unroll
        for (int i = 0; i < 2; i++) {
            int row = mbase + warp_m * 32 + i * 16 + gid;
#pragma unroll
            for (int j = 0; j < 4; j++) {
                int col = warp_n * 32 + j * 8 + tig * 2;
                atomicAdd(h2 + (size_t)row * HH + col,     acc[i][j][0]);
                atomicAdd(h2 + (size_t)row * HH + col + 1, acc[i][j][1]);
                atomicAdd(h2 + (size_t)(row + 8) * HH + col,     acc[i][j][2]);
                atomicAdd(h2 + (size_t)(row + 8) * HH + col + 1, acc[i][j][3]);
            }
        }
        return;
    }

    // store tile to smem (stages are dead now)
    float* yt = reinterpret_cast<float*>(sm);
    __syncthreads();   // all ldsm reads of stage smem complete
#pragma unroll
    for (int i = 0; i < 2; i++) {
        int rl = warp_m * 32 + i * 16 + gid;
#pragma unroll
        for (int j = 0; j < 4; j++) {
            int cl = warp_n * 32 + j * 8 + tig * 2;
            yt[rl * HH + cl]     = acc[i][j][0];
            yt[rl * HH + cl + 1] = acc[i][j][1];
            yt[(rl + 8) * HH + cl]     = acc[i][j][2];
            yt[(rl + 8) * HH + cl + 1] = acc[i][j][3];
        }
    }
    __syncthreads();

    // edge scatter: warp per edge; lane covers 4 cols
    const int ngr = 128 / npg;             // graphs covered by this block's rows
    const int gfirst = mbase / npg;
    for (int gi = 0; gi < ngr; gi++) {
        int ebase = (gfirst + gi) * EPG;
#pragma unroll 1
        for (int e = ebase + wid; e < ebase + EPG; e += 16) {
            if (!valid[e]) continue;
            float cf = (dblk < ED) ? ea[(size_t)e * ED + dblk] : 1.f;
            int sl = src[e] - mbase;
            float4 v = reinterpret_cast<const float4*>(yt + sl * HH)[lane];
            float* ag = h2 + (size_t)dst[e] * HH + lane * 4;
            atomicAdd(ag + 0, cf * v.x);
            atomicAdd(ag + 1, cf * v.y);
            atomicAdd(ag + 2, cf * v.z);
            atomicAdd(ag + 3, cf * v.w);
        }
    }
}

// ---------------- pipeline kernels ----------------
__global__ void init_edges_k(const int* __restrict__ ei, int* __restrict__ src,
                             int* __restrict__ dst, int* __restrict__ valid) {
    int e = blockIdx.x * blockDim.x + threadIdx.x;
    if (e < NE) { src[e] = ei[e]; dst[e] = ei[NE + e]; valid[e] = 1; }
}

// deterministic BN partials: block j sums rows j, j+64, ...
__global__ void bn_stats_k(const float* __restrict__ h, float* __restrict__ partial, int n) {
    int j = blockIdx.x, o = threadIdx.x;
    float s = 0.f, s2 = 0.f;
    for (int r = j; r < n; r += 64) {
        float v = h[(size_t)r * HH + o];
        s += v; s2 += v * v;
    }
    partial[j * 256 + o] = s;
    partial[j * 256 + 128 + o] = s2;
}

// fused: BN apply + ReLU + score + topk + gather(+scale) + split-A + edge remap.
__global__ void fused_pool_k(const float* __restrict__ h2, const float* __restrict__ partial,
                             const float* __restrict__ gamma, const float* __restrict__ beta,
                             const float* __restrict__ pw,
                             float* __restrict__ hout, __nv_bfloat16* __restrict__ Ab,
                             int* __restrict__ src, int* __restrict__ dst,
                             int* __restrict__ valid,
                             int npg, int kk, int n) {
    extern __shared__ float fs[];
    float* tile = fs;                       // npg * 129
    float* spw  = tile + npg * 129;         // 128
    float* sc   = spw + 128;                // npg
    float* red  = sc + npg;                 // 128
    int*   rankA = (int*)(red + 128);       // npg

    const int b = blockIdx.x, o = threadIdx.x;
    const int base = b * npg;

    float s = 0.f, s2 = 0.f;
#pragma unroll 8
    for (int j = 0; j < 64; j++) {
        s  += partial[j * 256 + o];
        s2 += partial[j * 256 + 128 + o];
    }
    float inv_n = 1.f / (float)n;
    float mu = s * inv_n;
    float var = s2 * inv_n - mu * mu;
    float scal = gamma[o] * rsqrtf(var + 1e-5f);
    float be = beta[o];

    float pwo = pw[o];
    spw[o] = pwo;
    red[o] = pwo * pwo;
    __syncthreads();
    for (int st = 64; st > 0; st >>= 1) {
        if (o < st) red[o] += red[o + st];
        __syncthreads();
    }
    float pwn = sqrtf(red[0]);

    for (int i = 0; i < npg; i++) {
        float v = h2[(size_t)(base + i) * HH + o];
        tile[i * 129 + o] = fmaxf(scal * (v - mu) + be, 0.f);
    }
    __syncthreads();

    if (o < npg) {
        float acc = 0.f;
#pragma unroll 16
        for (int c = 0; c < HH; c++) acc += tile[o * 129 + c] * spw[c];
        sc[o] = tanhf(acc / pwn);
    }
    __syncthreads();

    if (o < npg) {
        float mine = sc[o];
        int r = 0;
        for (int j = 0; j < npg; j++) {
            float sj = sc[j];
            r += (sj > mine) || (sj == mine && j < o);
        }
        rankA[o] = r;
    }
    __syncthreads();

    for (int i = 0; i < npg; i++) {
        int r = rankA[i];
        if (r < kk) {
            int nid = b * kk + r;
            float val = tile[i * 129 + o] * sc[i];
            hout[(size_t)nid * HH + o] = val;
            __nv_bfloat16 h1, h2b;
            split2(val, h1, h2b);
            __nv_bfloat16* row = Ab + (size_t)nid * (NSPLIT * HH) + o;
            row[0] = h1; row[HH] = h1; row[2 * HH] = h2b;
        }
    }

    for (int e = b * EPG + o; e < (b + 1) * EPG; e += 128) {
        if (valid[e]) {
            int rs = rankA[src[e] - base];
            int rd = rankA[dst[e] - base];
            if (rs < kk && rd < kk) { src[e] = b * kk + rs; dst[e] = b * kk + rd; }
            else valid[e] = 0;
        }
    }
}

// fused meanpool + 2-layer MLP + sigmoid; one block per graph, 128 threads
__global__ void readout_k(const float* __restrict__ h, const float* __restrict__ w1,
                          const float* __restrict__ b1, const float* __restrict__ w2,
                          const float* __restrict__ b2, float* __restrict__ out) {
    __shared__ float sg[HH];
    __shared__ float red[64];
    int b = blockIdx.x, o = threadIdx.x;
    float acc = 0.f;
#pragma unroll
    for (int i = 0; i < K3; i++) acc += h[(size_t)(b * K3 + i) * HH + o];
    sg[o] = acc * (1.f / K3);
    __syncthreads();
    if (o < 64) {
        float a = b1[o];
        for (int i = 0; i < HH; i++) a = fmaf(sg[i], w1[i * 64 + o], a);
        a = fmaxf(a, 0.f);
        red[o] = a * w2[o];
    }
    __syncthreads();
    for (int st = 32; st > 0; st >>= 1) {
        if (o < st) red[o] += red[o + st];
        __syncthreads();
    }
    if (o == 0) out[b] = 1.f / (1.f + expf(-(red[0] + b2[0])));
}

// ---------------- host ----------------
extern "C" void kernel_launch(void* const* d_in, const int* in_sizes, int n_in,
                              void* d_out, int out_size) {
    const float* x     = (const float*)d_in[0];
    const int*   ei    = (const int*)d_in[1];
    const float* ea    = (const float*)d_in[2];
    const float* nn1_w = (const float*)d_in[4];
    const float* nn1_b = (const float*)d_in[5];
    const float* root1 = (const float*)d_in[6];
    const float* bias1 = (const float*)d_in[7];
    const float* nn2_w = (const float*)d_in[8];
    const float* nn2_b = (const float*)d_in[9];
    const float* root2 = (const float*)d_in[10];
    const float* bias2 = (const float*)d_in[11];
    const float* nn3_w = (const float*)d_in[12];
    const float* nn3_b = (const float*)d_in[13];
    const float* root3 = (const float*)d_in[14];
    const float* bias3 = (const float*)d_in[15];
    const float* gamma1 = (const float*)d_in[16];
    const float* beta1  = (const float*)d_in[17];
    const float* gamma2 = (const float*)d_in[18];
    const float* beta2  = (const float*)d_in[19];
    const float* gamma3 = (const float*)d_in[20];
    const float* beta3  = (const float*)d_in[21];
    const float* pw1 = (const float*)d_in[22];
    const float* pw2 = (const float*)d_in[23];
    const float* pw3 = (const float*)d_in[24];
    const float* l1w = (const float*)d_in[25];
    const float* l1b = (const float*)d_in[26];
    const float* l2w = (const float*)d_in[27];
    const float* l2b = (const float*)d_in[28];
    float* out = (float*)d_out;

    float *hp, *h2p, *partp;
    __nv_bfloat16 *Abp, *Bbp;
    int *srcp, *dstp, *validp;
    cudaGetSymbolAddress((void**)&Abp, g_Ab);
    cudaGetSymbolAddress((void**)&Bbp, g_Bb);
    cudaGetSymbolAddress((void**)&hp, g_h);
    cudaGetSymbolAddress((void**)&h2p, g_h2);
    cudaGetSymbolAddress((void**)&partp, g_partial);
    cudaGetSymbolAddress((void**)&srcp, g_src);
    cudaGetSymbolAddress((void**)&dstp, g_dst);
    cudaGetSymbolAddress((void**)&validp, g_valid);

    cudaFuncSetAttribute(gemm_fused_k, cudaFuncAttributeMaxDynamicSharedMemorySize, GEMM_SMEM);
    const int POOL_SMEM = (NPG0 * 129 + 128 + 2 * NPG0 + 128) * 4;
    cudaFuncSetAttribute(fused_pool_k, cudaFuncAttributeMaxDynamicSharedMemorySize, POOL_SMEM);

    init_edges_k<<<(NE + 255) / 256, 256>>>(ei, srcp, dstp, validp);

    // ---- layer 1: n=4096, cin=64, Kp=192, npg=128 ----
    split_A_k<<<(NN0 * CIN0 + 255) / 256, 256>>>(x, Abp, NN0, CIN0);
    split_B_k<<<(NDB * HH * CIN0 + 255) / 256, 256>>>(nn1_w, nn1_b, root1, Bbp, CIN0);
    init_h2_k<<<NN0, HH>>>(bias1, h2p);
    gemm_fused_k<<<dim3(NDB, NN0 / 128), 512, GEMM_SMEM>>>(
        Abp, Bbp, ea, srcp, dstp, validp, h2p, NSPLIT * CIN0, NPG0);
    bn_stats_k<<<64, HH>>>(h2p, partp, NN0);
    fused_pool_k<<<NB, HH, (NPG0 * 129 + 128 + 2 * NPG0 + 128) * 4>>>(
        h2p, partp, gamma1, beta1, pw1, hp, Abp, srcp, dstp, validp, NPG0, K1, NN0);

    // ---- layer 2: n=2048, cin=128, Kp=384, npg=64 ----
    int n2 = NB * K1;
    split_B_k<<<(NDB * HH * HH + 255) / 256, 256>>>(nn2_w, nn2_b, root2, Bbp, HH);
    init_h2_k<<<n2, HH>>>(bias2, h2p);
    gemm_fused_k<<<dim3(NDB, n2 / 128), 512, GEMM_SMEM>>>(
        Abp, Bbp, ea, srcp, dstp, validp, h2p, NSPLIT * HH, K1);
    bn_stats_k<<<64, HH>>>(h2p, partp, n2);
    fused_pool_k<<<NB, HH, (K1 * 129 + 128 + 2 * K1 + 128) * 4>>>(
        h2p, partp, gamma2, beta2, pw2, hp, Abp, srcp, dstp, validp, K1, K2, n2);

    // ---- layer 3: n=1024, cin=128, Kp=384, npg=32 ----
    int n3 = NB * K2;
    split_B_k<<<(NDB * HH * HH + 255) / 256, 256>>>(nn3_w, nn3_b, root3, Bbp, HH);
    init_h2_k<<<n3, HH>>>(bias3, h2p);
    gemm_fused_k<<<dim3(NDB, n3 / 128), 512, GEMM_SMEM>>>(
        Abp, Bbp, ea, srcp, dstp, validp, h2p, NSPLIT * HH, K2);
    bn_stats_k<<<64, HH>>>(h2p, partp, n3);
    fused_pool_k<<<NB, HH, (K2 * 129 + 128 + 2 * K2 + 128) * 4>>>(
        h2p, partp, gamma3, beta3, pw3, hp, Abp, srcp, dstp, validp, K2, K3, n3);

    // ---- readout ----
    readout_k<<<NB, HH>>>(hp, l1w, l1b, l2w, l2b, out);
}

// round 9
// speedup vs baseline: 1.6457x; 1.6457x over previous
#include <cuda_runtime.h>
#include <cuda_bf16.h>
#include <math.h>
#include <stdint.h>

// Problem constants
#define NB   32
#define NPG0 128
#define NE   8192
#define EPG  (NE/NB)      // 256 edges per graph (contiguous slots, valid-flagged)
#define CIN0 64
#define ED   32
#define HH   128
#define CED  33           // 32 edge-feature slices + bias slice
#define NDB  34           // + root slice (diverted to h2 in epilogue)
#define YC   (CED*HH)     // 4224 (Y stride; root slice not stored)
#define K1   64
#define K2   32
#define K3   16
#define NN0  (NB*NPG0)    // 4096
#define NSPLIT 3

// ---------------- scratch ----------------
__device__ float g_y[NN0 * YC];                       // 69 MB
__device__ __nv_bfloat16 g_Ab[NN0 * NSPLIT * HH];
__device__ __nv_bfloat16 g_Bb1[(NDB * HH) * NSPLIT * CIN0];
__device__ __nv_bfloat16 g_Bb2[(NDB * HH) * NSPLIT * HH];
__device__ __nv_bfloat16 g_Bb3[(NDB * HH) * NSPLIT * HH];
__device__ float g_h[NN0 * HH];
__device__ float g_h2[NN0 * HH];
__device__ int   g_src[NE], g_dst[NE], g_valid[NE];
__device__ float g_partial[64 * 256];

// ---------------- helpers ----------------
__device__ __forceinline__ void split2(float x, __nv_bfloat16& h1, __nv_bfloat16& h2) {
    h1 = __float2bfloat16(x);
    h2 = __float2bfloat16(x - __bfloat162float(h1));
}
__device__ __forceinline__ uint32_t smem_u32(const void* p) {
    return (uint32_t)__cvta_generic_to_shared(p);
}
__device__ __forceinline__ void cp_async16(uint32_t saddr, const void* gaddr) {
    asm volatile("cp.async.cg.shared.global [%0], [%1], 16;" :: "r"(saddr), "l"(gaddr));
}
__device__ __forceinline__ void ldsm4(uint32_t& r0, uint32_t& r1, uint32_t& r2, uint32_t& r3,
                                      uint32_t addr) {
    asm volatile("ldmatrix.sync.aligned.m8n8.x4.shared.b16 {%0,%1,%2,%3}, [%4];"
                 : "=r"(r0), "=r"(r1), "=r"(r2), "=r"(r3) : "r"(addr));
}
__device__ __forceinline__ void mma16816(float* c, const uint32_t* a, const uint32_t* b) {
    asm volatile("mma.sync.aligned.m16n8k16.row.col.f32.bf16.bf16.f32 "
                 "{%0,%1,%2,%3}, {%4,%5,%6,%7}, {%8,%9}, {%0,%1,%2,%3};"
                 : "+f"(c[0]), "+f"(c[1]), "+f"(c[2]), "+f"(c[3])
                 : "r"(a[0]), "r"(a[1]), "r"(a[2]), "r"(a[3]), "r"(b[0]), "r"(b[1]));
}

// ---------------- fused prep: init_edges + split_A(layer1) + split_B(all 3 layers) ----
// Ab[r, j*cin+k], blocks [h1, h1, h2]
// BbT[t, j*cin+k], blocks [b1, b2, b1]; t = d*128+o;
//   d<32: W[(d*cin+k)*128+o]; d==32: bvec[k*128+o]; d==33: root[k*128+o]
__device__ __forceinline__ void split_B_elem(const float* __restrict__ W,
                                             const float* __restrict__ bvec,
                                             const float* __restrict__ root,
                                             __nv_bfloat16* __restrict__ Bb,
                                             int i, int cin) {
    int t = i / cin, k = i - t * cin;
    int d = t >> 7, o = t & 127;
    float w;
    if (d < ED)       w = W[(size_t)(d * cin + k) * HH + o];
    else if (d == ED) w = bvec[(size_t)k * HH + o];
    else              w = root[(size_t)k * HH + o];
    __nv_bfloat16 b1, b2;
    split2(w, b1, b2);
    __nv_bfloat16* row = Bb + (size_t)t * NSPLIT * cin + k;
    row[0] = b1; row[cin] = b2; row[2 * cin] = b1;
}

#define PREP_SEG0 32      // init_edges: 8192 / 256
#define PREP_SEG1 1024    // split_A layer1: 4096*64 / 256
#define PREP_SEG2 1088    // split_B1: 34*128*64 / 256
#define PREP_SEG3 2176    // split_B2: 34*128*128 / 256
#define PREP_SEG4 2176    // split_B3
#define PREP_BLOCKS (PREP_SEG0 + PREP_SEG1 + PREP_SEG2 + PREP_SEG3 + PREP_SEG4)

__global__ void prep_k(const int* __restrict__ ei, const float* __restrict__ x,
                       __nv_bfloat16* __restrict__ Ab,
                       const float* __restrict__ nn1_w, const float* __restrict__ nn1_b,
                       const float* __restrict__ root1, __nv_bfloat16* __restrict__ Bb1,
                       const float* __restrict__ nn2_w, const float* __restrict__ nn2_b,
                       const float* __restrict__ root2, __nv_bfloat16* __restrict__ Bb2,
                       const float* __restrict__ nn3_w, const float* __restrict__ nn3_b,
                       const float* __restrict__ root3, __nv_bfloat16* __restrict__ Bb3,
                       int* __restrict__ src, int* __restrict__ dst,
                       int* __restrict__ valid) {
    int blk = blockIdx.x;
    if (blk < PREP_SEG0) {
        int e = blk * 256 + threadIdx.x;
        src[e] = ei[e]; dst[e] = ei[NE + e]; valid[e] = 1;
        return;
    }
    blk -= PREP_SEG0;
    if (blk < PREP_SEG1) {
        int i = blk * 256 + threadIdx.x;          // < 4096*64
        int r = i >> 6, k = i & 63;
        __nv_bfloat16 h1, h2;
        split2(x[i], h1, h2);
        __nv_bfloat16* row = Ab + (size_t)r * NSPLIT * CIN0 + k;
        row[0] = h1; row[CIN0] = h1; row[2 * CIN0] = h2;
        return;
    }
    blk -= PREP_SEG1;
    if (blk < PREP_SEG2) {
        split_B_elem(nn1_w, nn1_b, root1, Bb1, blk * 256 + threadIdx.x, CIN0);
        return;
    }
    blk -= PREP_SEG2;
    if (blk < PREP_SEG3) {
        split_B_elem(nn2_w, nn2_b, root2, Bb2, blk * 256 + threadIdx.x, HH);
        return;
    }
    blk -= PREP_SEG3;
    split_B_elem(nn3_w, nn3_b, root3, Bb3, blk * 256 + threadIdx.x, HH);
}

// ---------------- raw mma.sync GEMM (R7 mainloop, unchanged) ----------------
// C[128,128] per block; 16 warps (4m x 4n), warp tile 32x32; BK=64; 3-stage cp.async.
// Block x == 33 -> h2 = acc + bias (root slice).
#define BK   64
#define SROW 72                // 64+8 bf16 per row slot (144B): conflict-free ldsm
#define STG  (128 * SROW)      // elems per matrix per stage
#define GEMM_SMEM (3 * 2 * STG * 2)   // 110592 bytes

__global__ __launch_bounds__(512, 2)
void gemm_mma_k(const __nv_bfloat16* __restrict__ Ab, const __nv_bfloat16* __restrict__ Bb,
                float* __restrict__ Y, const float* __restrict__ bias,
                float* __restrict__ h2, int Kp) {
    extern __shared__ __nv_bfloat16 sm[];
    const int tid = threadIdx.x;
    const int lane = tid & 31;
    const int wid = tid >> 5;
    const int warp_m = wid & 3;     // 0..3
    const int warp_n = wid >> 2;    // 0..3
    const int mbase = blockIdx.y * 128;
    const int nbase = blockIdx.x * 128;
    const int NC = Kp >> 6;

    float acc[2][4][4];
#pragma unroll
    for (int i = 0; i < 2; i++)
#pragma unroll
        for (int j = 0; j < 4; j++)
#pragma unroll
            for (int q = 0; q < 4; q++) acc[i][j][q] = 0.f;

    auto prefetch = [&](int cIdx, int s) {
        const int kc = cIdx * BK;
        __nv_bfloat16* base = sm + s * 2 * STG;
#pragma unroll
        for (int u = 0; u < 4; u++) {
            int q = tid + u * 512;           // 0..2047
            int isB = q >> 10;
            int qq = q & 1023;
            int r = qq >> 3, ch = qq & 7;
            const __nv_bfloat16* g = isB
                ? (Bb + (size_t)(nbase + r) * Kp + kc + ch * 8)
                : (Ab + (size_t)(mbase + r) * Kp + kc + ch * 8);
            cp_async16(smem_u32(base + isB * STG + r * SROW + ch * 8), g);
        }
        asm volatile("cp.async.commit_group;" ::: "memory");
    };

    prefetch(0, 0);
    if (NC > 1) prefetch(1, 1);

    for (int c = 0; c < NC; c++) {
        if (c + 1 < NC) asm volatile("cp.async.wait_group 1;" ::: "memory");
        else            asm volatile("cp.async.wait_group 0;" ::: "memory");
        __syncthreads();
        if (c + 2 < NC) prefetch(c + 2, (c + 2) % 3);

        const int s = c % 3;
        const uint32_t a_base = smem_u32(sm + s * 2 * STG);
        const uint32_t b_base = a_base + STG * 2;   // bytes

        uint32_t af[2][2][4];
        uint32_t bf[2][4][2];

        auto load_frags = [&](int kk, int buf) {
            int acol = kk * 16 + (lane >> 4) * 8;
#pragma unroll
            for (int i = 0; i < 2; i++) {
                int arow = warp_m * 32 + i * 16 + (lane & 15);
                ldsm4(af[buf][i][0], af[buf][i][1], af[buf][i][2], af[buf][i][3],
                      a_base + (uint32_t)(arow * SROW + acol) * 2);
            }
            int m8 = lane >> 3;
            int kcol = kk * 16 + (m8 & 1) * 8;
#pragma unroll
            for (int g = 0; g < 2; g++) {
                int nrow = warp_n * 32 + (2 * g + (m8 >> 1)) * 8 + (lane & 7);
                ldsm4(bf[buf][2 * g][0], bf[buf][2 * g][1],
                      bf[buf][2 * g + 1][0], bf[buf][2 * g + 1][1],
                      b_base + (uint32_t)(nrow * SROW + kcol) * 2);
            }
        };

        load_frags(0, 0);
#pragma unroll
        for (int kk = 0; kk < 4; kk++) {
            int cur = kk & 1;
            if (kk < 3) load_frags(kk + 1, cur ^ 1);
#pragma unroll
            for (int i = 0; i < 2; i++)
#pragma unroll
                for (int j = 0; j < 4; j++)
                    mma16816(acc[i][j], af[cur][i], bf[cur][j]);
        }
    }

    // epilogue
    const int gid = lane >> 2, tig = lane & 3;
    if (blockIdx.x == 33) {
#pragma unroll
        for (int i = 0; i < 2; i++) {
            int row = mbase + warp_m * 32 + i * 16 + gid;
#pragma unroll
            for (int j = 0; j < 4; j++) {
                int col = warp_n * 32 + j * 8 + tig * 2;
                float b0 = bias[col], b1 = bias[col + 1];
                float* d0 = h2 + (size_t)row * HH + col;
                d0[0] = acc[i][j][0] + b0;
                d0[1] = acc[i][j][1] + b1;
                float* d1 = h2 + (size_t)(row + 8) * HH + col;
                d1[0] = acc[i][j][2] + b0;
                d1[1] = acc[i][j][3] + b1;
            }
        }
    } else {
#pragma unroll
        for (int i = 0; i < 2; i++) {
            int row = mbase + warp_m * 32 + i * 16 + gid;
#pragma unroll
            for (int j = 0; j < 4; j++) {
                int col = nbase + warp_n * 32 + j * 8 + tig * 2;
                *reinterpret_cast<float2*>(Y + (size_t)row * YC + col) =
                    make_float2(acc[i][j][0], acc[i][j][1]);
                *reinterpret_cast<float2*>(Y + (size_t)(row + 8) * YC + col) =
                    make_float2(acc[i][j][2], acc[i][j][3]);
            }
        }
    }
}

// ---------------- pipeline kernels (R7, unchanged) ----------------
// warp-per-edge, float4 lanes, coefficients via shuffle (no smem / block sync)
__global__ void edge_msg_k(const float* __restrict__ ea, const float* __restrict__ y,
                           float* __restrict__ agg, const int* __restrict__ src,
                           const int* __restrict__ dst, const int* __restrict__ valid) {
    int e = blockIdx.x * 4 + (threadIdx.x >> 5);
    int lane = threadIdx.x & 31;
    if (!valid[e]) return;
    float av = ea[(size_t)e * ED + lane];          // lane d holds a[e,d]
    const float4* yr = reinterpret_cast<const float4*>(y + (size_t)src[e] * YC) + lane;
    float4 acc = make_float4(0.f, 0.f, 0.f, 0.f);
#pragma unroll
    for (int d = 0; d < ED; d++) {
        float ad = __shfl_sync(0xffffffffu, av, d);
        float4 v = yr[d * 32];
        acc.x = fmaf(ad, v.x, acc.x);
        acc.y = fmaf(ad, v.y, acc.y);
        acc.z = fmaf(ad, v.z, acc.z);
        acc.w = fmaf(ad, v.w, acc.w);
    }
    {   // bias slice d=32, coefficient 1
        float4 v = yr[ED * 32];
        acc.x += v.x; acc.y += v.y; acc.z += v.z; acc.w += v.w;
    }
    float* ag = agg + (size_t)dst[e] * HH + lane * 4;
    atomicAdd(ag + 0, acc.x);
    atomicAdd(ag + 1, acc.y);
    atomicAdd(ag + 2, acc.z);
    atomicAdd(ag + 3, acc.w);
}

// deterministic BN partials: block j sums rows j, j+64, ...
__global__ void bn_stats_k(const float* __restrict__ h, float* __restrict__ partial, int n) {
    int j = blockIdx.x, o = threadIdx.x;
    float s = 0.f, s2 = 0.f;
    for (int r = j; r < n; r += 64) {
        float v = h[(size_t)r * HH + o];
        s += v; s2 += v * v;
    }
    partial[j * 256 + o] = s;
    partial[j * 256 + 128 + o] = s2;
}

// fused: BN apply + ReLU + score + topk + gather(+scale) + split-A + edge remap.
__global__ void fused_pool_k(const float* __restrict__ h2, const float* __restrict__ partial,
                             const float* __restrict__ gamma, const float* __restrict__ beta,
                             const float* __restrict__ pw,
                             float* __restrict__ hout, __nv_bfloat16* __restrict__ Ab,
                             int* __restrict__ src, int* __restrict__ dst,
                             int* __restrict__ valid,
                             int npg, int kk, int n) {
    extern __shared__ float fs[];
    float* tile = fs;                       // npg * 129
    float* spw  = tile + npg * 129;         // 128
    float* sc   = spw + 128;                // npg
    float* red  = sc + npg;                 // 128
    int*   rankA = (int*)(red + 128);       // npg

    const int b = blockIdx.x, o = threadIdx.x;
    const int base = b * npg;

    float s = 0.f, s2 = 0.f;
#pragma unroll 8
    for (int j = 0; j < 64; j++) {
        s  += partial[j * 256 + o];
        s2 += partial[j * 256 + 128 + o];
    }
    float inv_n = 1.f / (float)n;
    float mu = s * inv_n;
    float var = s2 * inv_n - mu * mu;
    float scal = gamma[o] * rsqrtf(var + 1e-5f);
    float be = beta[o];

    float pwo = pw[o];
    spw[o] = pwo;
    red[o] = pwo * pwo;
    __syncthreads();
    for (int st = 64; st > 0; st >>= 1) {
        if (o < st) red[o] += red[o + st];
        __syncthreads();
    }
    float pwn = sqrtf(red[0]);

    for (int i = 0; i < npg; i++) {
        float v = h2[(size_t)(base + i) * HH + o];
        tile[i * 129 + o] = fmaxf(scal * (v - mu) + be, 0.f);
    }
    __syncthreads();

    if (o < npg) {
        float acc = 0.f;
#pragma unroll 16
        for (int c = 0; c < HH; c++) acc += tile[o * 129 + c] * spw[c];
        sc[o] = tanhf(acc / pwn);
    }
    __syncthreads();

    if (o < npg) {
        float mine = sc[o];
        int r = 0;
        for (int j = 0; j < npg; j++) {
            float sj = sc[j];
            r += (sj > mine) || (sj == mine && j < o);
        }
        rankA[o] = r;
    }
    __syncthreads();

    for (int i = 0; i < npg; i++) {
        int r = rankA[i];
        if (r < kk) {
            int nid = b * kk + r;
            float val = tile[i * 129 + o] * sc[i];
            hout[(size_t)nid * HH + o] = val;
            __nv_bfloat16 h1, h2b;
            split2(val, h1, h2b);
            __nv_bfloat16* row = Ab + (size_t)nid * (NSPLIT * HH) + o;
            row[0] = h1; row[HH] = h1; row[2 * HH] = h2b;
        }
    }

    for (int e = b * EPG + o; e < (b + 1) * EPG; e += 128) {
        if (valid[e]) {
            int rs = rankA[src[e] - base];
            int rd = rankA[dst[e] - base];
            if (rs < kk && rd < kk) { src[e] = b * kk + rs; dst[e] = b * kk + rd; }
            else valid[e] = 0;
        }
    }
}

// fused meanpool + 2-layer MLP + sigmoid; one block per graph, 128 threads
__global__ void readout_k(const float* __restrict__ h, const float* __restrict__ w1,
                          const float* __restrict__ b1, const float* __restrict__ w2,
                          const float* __restrict__ b2, float* __restrict__ out) {
    __shared__ float sg[HH];
    __shared__ float red[64];
    int b = blockIdx.x, o = threadIdx.x;
    float acc = 0.f;
#pragma unroll
    for (int i = 0; i < K3; i++) acc += h[(size_t)(b * K3 + i) * HH + o];
    sg[o] = acc * (1.f / K3);
    __syncthreads();
    if (o < 64) {
        float a = b1[o];
        for (int i = 0; i < HH; i++) a = fmaf(sg[i], w1[i * 64 + o], a);
        a = fmaxf(a, 0.f);
        red[o] = a * w2[o];
    }
    __syncthreads();
    for (int st = 32; st > 0; st >>= 1) {
        if (o < st) red[o] += red[o + st];
        __syncthreads();
    }
    if (o == 0) out[b] = 1.f / (1.f + expf(-(red[0] + b2[0])));
}

// ---------------- host ----------------
extern "C" void kernel_launch(void* const* d_in, const int* in_sizes, int n_in,
                              void* d_out, int out_size) {
    const float* x     = (const float*)d_in[0];
    const int*   ei    = (const int*)d_in[1];
    const float* ea    = (const float*)d_in[2];
    const float* nn1_w = (const float*)d_in[4];
    const float* nn1_b = (const float*)d_in[5];
    const float* root1 = (const float*)d_in[6];
    const float* bias1 = (const float*)d_in[7];
    const float* nn2_w = (const float*)d_in[8];
    const float* nn2_b = (const float*)d_in[9];
    const float* root2 = (const float*)d_in[10];
    const float* bias2 = (const float*)d_in[11];
    const float* nn3_w = (const float*)d_in[12];
    const float* nn3_b = (const float*)d_in[13];
    const float* root3 = (const float*)d_in[14];
    const float* bias3 = (const float*)d_in[15];
    const float* gamma1 = (const float*)d_in[16];
    const float* beta1  = (const float*)d_in[17];
    const float* gamma2 = (const float*)d_in[18];
    const float* beta2  = (const float*)d_in[19];
    const float* gamma3 = (const float*)d_in[20];
    const float* beta3  = (const float*)d_in[21];
    const float* pw1 = (const float*)d_in[22];
    const float* pw2 = (const float*)d_in[23];
    const float* pw3 = (const float*)d_in[24];
    const float* l1w = (const float*)d_in[25];
    const float* l1b = (const float*)d_in[26];
    const float* l2w = (const float*)d_in[27];
    const float* l2b = (const float*)d_in[28];
    float* out = (float*)d_out;

    float *yp, *hp, *h2p, *partp;
    __nv_bfloat16 *Abp, *Bb1p, *Bb2p, *Bb3p;
    int *srcp, *dstp, *validp;
    cudaGetSymbolAddress((void**)&yp, g_y);
    cudaGetSymbolAddress((void**)&Abp, g_Ab);
    cudaGetSymbolAddress((void**)&Bb1p, g_Bb1);
    cudaGetSymbolAddress((void**)&Bb2p, g_Bb2);
    cudaGetSymbolAddress((void**)&Bb3p, g_Bb3);
    cudaGetSymbolAddress((void**)&hp, g_h);
    cudaGetSymbolAddress((void**)&h2p, g_h2);
    cudaGetSymbolAddress((void**)&partp, g_partial);
    cudaGetSymbolAddress((void**)&srcp, g_src);
    cudaGetSymbolAddress((void**)&dstp, g_dst);
    cudaGetSymbolAddress((void**)&validp, g_valid);

    cudaFuncSetAttribute(gemm_mma_k, cudaFuncAttributeMaxDynamicSharedMemorySize, GEMM_SMEM);
    const int POOL_SMEM = (NPG0 * 129 + 128 + 2 * NPG0 + 128) * 4;
    cudaFuncSetAttribute(fused_pool_k, cudaFuncAttributeMaxDynamicSharedMemorySize, POOL_SMEM);

    // ---- fused prep (edges + split_A + all split_B) ----
    prep_k<<<PREP_BLOCKS, 256>>>(ei, x, Abp,
                                 nn1_w, nn1_b, root1, Bb1p,
                                 nn2_w, nn2_b, root2, Bb2p,
                                 nn3_w, nn3_b, root3, Bb3p,
                                 srcp, dstp, validp);

    // ---- layer 1: n=4096, cin=64, Kp=192 ----
    gemm_mma_k<<<dim3(NDB, NN0 / 128), 512, GEMM_SMEM>>>(Abp, Bb1p, yp, bias1, h2p,
                                                         NSPLIT * CIN0);
    edge_msg_k<<<NE / 4, 128>>>(ea, yp, h2p, srcp, dstp, validp);
    bn_stats_k<<<64, HH>>>(h2p, partp, NN0);
    fused_pool_k<<<NB, HH, (NPG0 * 129 + 128 + 2 * NPG0 + 128) * 4>>>(
        h2p, partp, gamma1, beta1, pw1, hp, Abp, srcp, dstp, validp, NPG0, K1, NN0);

    // ---- layer 2: n=2048, cin=128, Kp=384 ----
    int n2 = NB * K1;
    gemm_mma_k<<<dim3(NDB, n2 / 128), 512, GEMM_SMEM>>>(Abp, Bb2p, yp, bias2, h2p,
                                                        NSPLIT * HH);
    edge_msg_k<<<NE / 4, 128>>>(ea, yp, h2p, srcp, dstp, validp);
    bn_stats_k<<<64, HH>>>(h2p, partp, n2);
    fused_pool_k<<<NB, HH, (K1 * 129 + 128 + 2 * K1 + 128) * 4>>>(
        h2p, partp, gamma2, beta2, pw2, hp, Abp, srcp, dstp, validp, K1, K2, n2);

    // ---- layer 3: n=1024, cin=128, Kp=384 ----
    int n3 = NB * K2;
    gemm_mma_k<<<dim3(NDB, n3 / 128), 512, GEMM_SMEM>>>(Abp, Bb3p, yp, bias3, h2p,
                                                        NSPLIT * HH);
    edge_msg_k<<<NE / 4, 128>>>(ea, yp, h2p, srcp, dstp, validp);
    bn_stats_k<<<64, HH>>>(h2p, partp, n3);
    fused_pool_k<<<NB, HH, (K2 * 129 + 128 + 2 * K2 + 128) * 4>>>(
        h2p, partp, gamma3, beta3, pw3, hp, Abp, srcp, dstp, validp, K2, K3, n3);

    // ---- readout ----
    readout_k<<<NB, HH>>>(hp, l1w, l1b, l2w, l2b, out);
}

// round 11
// speedup vs baseline: 1.6634x; 1.0108x over previous
#include <cuda_runtime.h>
#include <cuda_bf16.h>
#include <math.h>
#include <stdint.h>

// Problem constants
#define NB   32
#define NPG0 128
#define NE   8192
#define EPG  (NE/NB)      // 256 edges per graph (contiguous slots, valid-flagged)
#define CIN0 64
#define ED   32
#define HH   128
#define CED  33           // 32 edge-feature slices + bias slice
#define NDB  34           // + root slice (diverted to h2 in epilogue)
#define YC   (CED*HH)     // 4224 (Y stride; root slice not stored)
#define K1   64
#define K2   32
#define K3   16
#define NN0  (NB*NPG0)    // 4096

// ---------------- scratch ----------------
__device__ float g_y[NN0 * YC];                       // 69 MB
__device__ __nv_bfloat16 g_Ab[NN0 * 2 * HH];          // [h1 | h2]
__device__ __nv_bfloat16 g_Bb1[(NDB * HH) * 2 * CIN0]; // [b1 | b2]
__device__ __nv_bfloat16 g_Bb2[(NDB * HH) * 2 * HH];
__device__ __nv_bfloat16 g_Bb3[(NDB * HH) * 2 * HH];
__device__ float g_h[NN0 * HH];
__device__ float g_h2[NN0 * HH];
__device__ int   g_src[NE], g_dst[NE], g_valid[NE];
__device__ float g_partial[256 * 256];

// ---------------- helpers ----------------
__device__ __forceinline__ void split2(float x, __nv_bfloat16& h1, __nv_bfloat16& h2) {
    h1 = __float2bfloat16(x);
    h2 = __float2bfloat16(x - __bfloat162float(h1));
}
__device__ __forceinline__ uint32_t smem_u32(const void* p) {
    return (uint32_t)__cvta_generic_to_shared(p);
}
__device__ __forceinline__ void cp_async16(uint32_t saddr, const void* gaddr) {
    asm volatile("cp.async.cg.shared.global [%0], [%1], 16;" :: "r"(saddr), "l"(gaddr));
}
__device__ __forceinline__ void ldsm4(uint32_t& r0, uint32_t& r1, uint32_t& r2, uint32_t& r3,
                                      uint32_t addr) {
    asm volatile("ldmatrix.sync.aligned.m8n8.x4.shared.b16 {%0,%1,%2,%3}, [%4];"
                 : "=r"(r0), "=r"(r1), "=r"(r2), "=r"(r3) : "r"(addr));
}
__device__ __forceinline__ void mma16816(float* c, const uint32_t* a, const uint32_t* b) {
    asm volatile("mma.sync.aligned.m16n8k16.row.col.f32.bf16.bf16.f32 "
                 "{%0,%1,%2,%3}, {%4,%5,%6,%7}, {%8,%9}, {%0,%1,%2,%3};"
                 : "+f"(c[0]), "+f"(c[1]), "+f"(c[2]), "+f"(c[3])
                 : "r"(a[0]), "r"(a[1]), "r"(a[2]), "r"(a[3]), "r"(b[0]), "r"(b[1]));
}

// ---------------- fused prep: init_edges + split_A(layer1) + split_B(all 3 layers) ----
// Ab[r, {h1(cin) | h2(cin)}] ; BbT[t, {b1(cin) | b2(cin)}], t = d*128+o;
//   d<32: W[(d*cin+k)*128+o]; d==32: bvec[k*128+o]; d==33: root[k*128+o]
__device__ __forceinline__ void split_B_elem(const float* __restrict__ W,
                                             const float* __restrict__ bvec,
                                             const float* __restrict__ root,
                                             __nv_bfloat16* __restrict__ Bb,
                                             int i, int cin) {
    int t = i / cin, k = i - t * cin;
    int d = t >> 7, o = t & 127;
    float w;
    if (d < ED)       w = W[(size_t)(d * cin + k) * HH + o];
    else if (d == ED) w = bvec[(size_t)k * HH + o];
    else              w = root[(size_t)k * HH + o];
    __nv_bfloat16 b1, b2;
    split2(w, b1, b2);
    __nv_bfloat16* row = Bb + (size_t)t * 2 * cin + k;
    row[0] = b1; row[cin] = b2;
}

#define PREP_SEG0 32      // init_edges: 8192 / 256
#define PREP_SEG1 1024    // split_A layer1: 4096*64 / 256
#define PREP_SEG2 1088    // split_B1: 34*128*64 / 256
#define PREP_SEG3 2176    // split_B2: 34*128*128 / 256
#define PREP_SEG4 2176    // split_B3
#define PREP_BLOCKS (PREP_SEG0 + PREP_SEG1 + PREP_SEG2 + PREP_SEG3 + PREP_SEG4)

__global__ void prep_k(const int* __restrict__ ei, const float* __restrict__ x,
                       __nv_bfloat16* __restrict__ Ab,
                       const float* __restrict__ nn1_w, const float* __restrict__ nn1_b,
                       const float* __restrict__ root1, __nv_bfloat16* __restrict__ Bb1,
                       const float* __restrict__ nn2_w, const float* __restrict__ nn2_b,
                       const float* __restrict__ root2, __nv_bfloat16* __restrict__ Bb2,
                       const float* __restrict__ nn3_w, const float* __restrict__ nn3_b,
                       const float* __restrict__ root3, __nv_bfloat16* __restrict__ Bb3,
                       int* __restrict__ src, int* __restrict__ dst,
                       int* __restrict__ valid) {
    int blk = blockIdx.x;
    if (blk < PREP_SEG0) {
        int e = blk * 256 + threadIdx.x;
        src[e] = ei[e]; dst[e] = ei[NE + e]; valid[e] = 1;
        return;
    }
    blk -= PREP_SEG0;
    if (blk < PREP_SEG1) {
        int i = blk * 256 + threadIdx.x;          // < 4096*64
        int r = i >> 6, k = i & 63;
        __nv_bfloat16 h1, h2;
        split2(x[i], h1, h2);
        __nv_bfloat16* row = Ab + (size_t)r * 2 * CIN0 + k;
        row[0] = h1; row[CIN0] = h2;
        return;
    }
    blk -= PREP_SEG1;
    if (blk < PREP_SEG2) {
        split_B_elem(nn1_w, nn1_b, root1, Bb1, blk * 256 + threadIdx.x, CIN0);
        return;
    }
    blk -= PREP_SEG2;
    if (blk < PREP_SEG3) {
        split_B_elem(nn2_w, nn2_b, root2, Bb2, blk * 256 + threadIdx.x, HH);
        return;
    }
    blk -= PREP_SEG3;
    split_B_elem(nn3_w, nn3_b, root3, Bb3, blk * 256 + threadIdx.x, HH);
}

// ---------------- raw mma.sync GEMM with A/B register-reuse over split pairs -------
// C[128,128] per block; 8 warps (4m x 2n), warp tile 32x64.
// K organized as 64-col chunks: chunk(2p)=(h1[p],b1[p]), chunk(2p+1)=(h2[p],b2[p]).
// Products per pair: h1*b1 + h2*b1 + h1*b2 (exact 3-term split, 2/3 the memory traffic).
// Ring schedule (FIXED from R10): pre-load chunks 0,1,2; after consuming pair p,
// prefetch chunk 2p+3 into the stage chunk 2p just vacated.
// Block x == 33 -> h2agg = acc + bias (root slice).
#define SROW 72                // 64+8 bf16 per row slot (144B)
#define STG  (128 * SROW)      // elems per matrix per stage
#define GEMM_SMEM (3 * 2 * STG * 2)   // 110592 bytes, 3 stages

__global__ __launch_bounds__(256, 2)
void gemm_mma_k(const __nv_bfloat16* __restrict__ Ab, const __nv_bfloat16* __restrict__ Bb,
                float* __restrict__ Y, const float* __restrict__ bias,
                float* __restrict__ h2agg, int cin) {
    extern __shared__ __nv_bfloat16 sm[];
    const int tid = threadIdx.x;
    const int lane = tid & 31;
    const int wid = tid >> 5;
    const int warp_m = wid & 3;     // 0..3 -> 32-row slice
    const int warp_n = wid >> 2;    // 0..1 -> 64-col slice
    const int mbase = blockIdx.y * 128;
    const int nbase = blockIdx.x * 128;
    const int Kp2 = 2 * cin;
    const int NPAIR = cin >> 6;
    const int NCH = NPAIR * 2;

    float acc[2][8][4];
#pragma unroll
    for (int i = 0; i < 2; i++)
#pragma unroll
        for (int j = 0; j < 8; j++)
#pragma unroll
            for (int q = 0; q < 4; q++) acc[i][j][q] = 0.f;

    // chunk c: cols [ (c&1)*cin + (c>>1)*64 , +64 ) of Ab/Bb; -> stage c%3
    auto prefetch = [&](int c) {
        const int s = c % 3;
        const int kc = (c & 1) * cin + ((c >> 1) << 6);
        __nv_bfloat16* base = sm + s * 2 * STG;
#pragma unroll
        for (int u = 0; u < 8; u++) {
            int q = tid + u * 256;            // 0..2047
            int isB = q >> 10;
            int qq = q & 1023;
            int r = qq >> 3, ch = qq & 7;
            const __nv_bfloat16* g = isB
                ? (Bb + (size_t)(nbase + r) * Kp2 + kc + ch * 8)
                : (Ab + (size_t)(mbase + r) * Kp2 + kc + ch * 8);
            cp_async16(smem_u32(base + isB * STG + r * SROW + ch * 8), g);
        }
        asm volatile("cp.async.commit_group;" ::: "memory");
    };

    prefetch(0);
    prefetch(1);
    if (NCH > 2) prefetch(2);      // stage 2 is free from the start

    for (int p = 0; p < NPAIR; p++) {
        // chunks 2p, 2p+1 must be resident; chunk 2p+2 (if issued) may stay in flight
        if (2 * p + 2 < NCH) asm volatile("cp.async.wait_group 1;" ::: "memory");
        else                 asm volatile("cp.async.wait_group 0;" ::: "memory");
        __syncthreads();

        const int sA = (2 * p) % 3, sB = (2 * p + 1) % 3;
        const uint32_t a1_base = smem_u32(sm + sA * 2 * STG);         // h1
        const uint32_t b1_base = a1_base + STG * 2;                   // b1 (bytes)
        const uint32_t a2_base = smem_u32(sm + sB * 2 * STG);         // h2
        const uint32_t b2_base = a2_base + STG * 2;                   // b2

        const int m8 = lane >> 3;
        const int arow_off = warp_m * 32 + (lane & 15);
        const int acol_sel = (lane >> 4) * 8;
        const int brow0 = warp_n * 64 + (m8 >> 1) * 8 + (lane & 7);
        const int bcol_sel = (m8 & 1) * 8;

#pragma unroll
        for (int kk = 0; kk < 4; kk++) {
            const uint32_t aoff = (uint32_t)(kk * 16 + acol_sel) * 2;
            const uint32_t boff = (uint32_t)(kk * 16 + bcol_sel) * 2;

            uint32_t af1[2][4];
#pragma unroll
            for (int i = 0; i < 2; i++)
                ldsm4(af1[i][0], af1[i][1], af1[i][2], af1[i][3],
                      a1_base + (uint32_t)((arow_off + i * 16) * SROW) * 2 + aoff);
            uint32_t bf1[8][2];
#pragma unroll
            for (int g = 0; g < 4; g++)
                ldsm4(bf1[2 * g][0], bf1[2 * g][1], bf1[2 * g + 1][0], bf1[2 * g + 1][1],
                      b1_base + (uint32_t)((brow0 + g * 16) * SROW) * 2 + boff);
#pragma unroll
            for (int i = 0; i < 2; i++)
#pragma unroll
                for (int j = 0; j < 8; j++)
                    mma16816(acc[i][j], af1[i], bf1[j]);

            uint32_t af2[2][4];
#pragma unroll
            for (int i = 0; i < 2; i++)
                ldsm4(af2[i][0], af2[i][1], af2[i][2], af2[i][3],
                      a2_base + (uint32_t)((arow_off + i * 16) * SROW) * 2 + aoff);
#pragma unroll
            for (int i = 0; i < 2; i++)
#pragma unroll
                for (int j = 0; j < 8; j++)
                    mma16816(acc[i][j], af2[i], bf1[j]);

            uint32_t bf2[8][2];
#pragma unroll
            for (int g = 0; g < 4; g++)
                ldsm4(bf2[2 * g][0], bf2[2 * g][1], bf2[2 * g + 1][0], bf2[2 * g + 1][1],
                      b2_base + (uint32_t)((brow0 + g * 16) * SROW) * 2 + boff);
#pragma unroll
            for (int i = 0; i < 2; i++)
#pragma unroll
                for (int j = 0; j < 8; j++)
                    mma16816(acc[i][j], af1[i], bf2[j]);
        }

        // prefetch the second chunk of the next pair into the stage chunk 2p vacated
        if (2 * p + 3 < NCH) {
            __syncthreads();               // all warps done reading stage (2p)%3
            prefetch(2 * p + 3);
        }
    }

    // epilogue: c-frag: {c0,c1}=C[gid][tig*2..+1], {c2,c3}=C[gid+8][tig*2..+1]
    const int gid = lane >> 2, tig = lane & 3;
    if (blockIdx.x == 33) {
#pragma unroll
        for (int i = 0; i < 2; i++) {
            int row = mbase + warp_m * 32 + i * 16 + gid;
#pragma unroll
            for (int j = 0; j < 8; j++) {
                int col = warp_n * 64 + j * 8 + tig * 2;
                float b0 = bias[col], b1 = bias[col + 1];
                float* d0 = h2agg + (size_t)row * HH + col;
                d0[0] = acc[i][j][0] + b0;
                d0[1] = acc[i][j][1] + b1;
                float* d1 = h2agg + (size_t)(row + 8) * HH + col;
                d1[0] = acc[i][j][2] + b0;
                d1[1] = acc[i][j][3] + b1;
            }
        }
    } else {
#pragma unroll
        for (int i = 0; i < 2; i++) {
            int row = mbase + warp_m * 32 + i * 16 + gid;
#pragma unroll
            for (int j = 0; j < 8; j++) {
                int col = nbase + warp_n * 64 + j * 8 + tig * 2;
                *reinterpret_cast<float2*>(Y + (size_t)row * YC + col) =
                    make_float2(acc[i][j][0], acc[i][j][1]);
                *reinterpret_cast<float2*>(Y + (size_t)(row + 8) * YC + col) =
                    make_float2(acc[i][j][2], acc[i][j][3]);
            }
        }
    }
}

// ---------------- pipeline kernels ----------------
// warp-per-edge, float4 lanes, coefficients via shuffle (no smem / block sync)
__global__ void edge_msg_k(const float* __restrict__ ea, const float* __restrict__ y,
                           float* __restrict__ agg, const int* __restrict__ src,
                           const int* __restrict__ dst, const int* __restrict__ valid) {
    int e = blockIdx.x * 4 + (threadIdx.x >> 5);
    int lane = threadIdx.x & 31;
    if (!valid[e]) return;
    float av = ea[(size_t)e * ED + lane];          // lane d holds a[e,d]
    const float4* yr = reinterpret_cast<const float4*>(y + (size_t)src[e] * YC) + lane;
    float4 acc = make_float4(0.f, 0.f, 0.f, 0.f);
#pragma unroll
    for (int d = 0; d < ED; d++) {
        float ad = __shfl_sync(0xffffffffu, av, d);
        float4 v = yr[d * 32];
        acc.x = fmaf(ad, v.x, acc.x);
        acc.y = fmaf(ad, v.y, acc.y);
        acc.z = fmaf(ad, v.z, acc.z);
        acc.w = fmaf(ad, v.w, acc.w);
    }
    {   // bias slice d=32, coefficient 1
        float4 v = yr[ED * 32];
        acc.x += v.x; acc.y += v.y; acc.z += v.z; acc.w += v.w;
    }
    float* ag = agg + (size_t)dst[e] * HH + lane * 4;
    atomicAdd(ag + 0, acc.x);
    atomicAdd(ag + 1, acc.y);
    atomicAdd(ag + 2, acc.z);
    atomicAdd(ag + 3, acc.w);
}

// deterministic BN partials: block j sums rows j, j+256, ... (256 blocks: latency fix)
__global__ void bn_stats_k(const float* __restrict__ h, float* __restrict__ partial, int n) {
    int j = blockIdx.x, o = threadIdx.x;
    float s = 0.f, s2 = 0.f;
    for (int r = j; r < n; r += 256) {
        float v = h[(size_t)r * HH + o];
        s += v; s2 += v * v;
    }
    partial[j * 256 + o] = s;
    partial[j * 256 + 128 + o] = s2;
}

// fused: BN apply + ReLU + score + topk + gather(+scale) + split-A + edge remap.
__global__ void fused_pool_k(const float* __restrict__ h2, const float* __restrict__ partial,
                             const float* __restrict__ gamma, const float* __restrict__ beta,
                             const float* __restrict__ pw,
                             float* __restrict__ hout, __nv_bfloat16* __restrict__ Ab,
                             int* __restrict__ src, int* __restrict__ dst,
                             int* __restrict__ valid,
                             int npg, int kk, int n) {
    extern __shared__ float fs[];
    float* tile = fs;                       // npg * 129
    float* spw  = tile + npg * 129;         // 128
    float* sc   = spw + 128;                // npg
    float* red  = sc + npg;                 // 128
    int*   rankA = (int*)(red + 128);       // npg

    const int b = blockIdx.x, o = threadIdx.x;
    const int base = b * npg;

    float s = 0.f, s2 = 0.f;
#pragma unroll 8
    for (int j = 0; j < 256; j++) {
        s  += partial[j * 256 + o];
        s2 += partial[j * 256 + 128 + o];
    }
    float inv_n = 1.f / (float)n;
    float mu = s * inv_n;
    float var = s2 * inv_n - mu * mu;
    float scal = gamma[o] * rsqrtf(var + 1e-5f);
    float be = beta[o];

    float pwo = pw[o];
    spw[o] = pwo;
    red[o] = pwo * pwo;
    __syncthreads();
    for (int st = 64; st > 0; st >>= 1) {
        if (o < st) red[o] += red[o + st];
        __syncthreads();
    }
    float pwn = sqrtf(red[0]);

    for (int i = 0; i < npg; i++) {
        float v = h2[(size_t)(base + i) * HH + o];
        tile[i * 129 + o] = fmaxf(scal * (v - mu) + be, 0.f);
    }
    __syncthreads();

    if (o < npg) {
        float acc = 0.f;
#pragma unroll 16
        for (int c = 0; c < HH; c++) acc += tile[o * 129 + c] * spw[c];
        sc[o] = tanhf(acc / pwn);
    }
    __syncthreads();

    if (o < npg) {
        float mine = sc[o];
        int r = 0;
        for (int j = 0; j < npg; j++) {
            float sj = sc[j];
            r += (sj > mine) || (sj == mine && j < o);
        }
        rankA[o] = r;
    }
    __syncthreads();

    for (int i = 0; i < npg; i++) {
        int r = rankA[i];
        if (r < kk) {
            int nid = b * kk + r;
            float val = tile[i * 129 + o] * sc[i];
            hout[(size_t)nid * HH + o] = val;
            __nv_bfloat16 h1, h2b;
            split2(val, h1, h2b);
            __nv_bfloat16* row = Ab + (size_t)nid * (2 * HH) + o;
            row[0] = h1; row[HH] = h2b;
        }
    }

    for (int e = b * EPG + o; e < (b + 1) * EPG; e += 128) {
        if (valid[e]) {
            int rs = rankA[src[e] - base];
            int rd = rankA[dst[e] - base];
            if (rs < kk && rd < kk) { src[e] = b * kk + rs; dst[e] = b * kk + rd; }
            else valid[e] = 0;
        }
    }
}

// fused meanpool + 2-layer MLP + sigmoid; one block per graph, 128 threads
__global__ void readout_k(const float* __restrict__ h, const float* __restrict__ w1,
                          const float* __restrict__ b1, const float* __restrict__ w2,
                          const float* __restrict__ b2, float* __restrict__ out) {
    __shared__ float sg[HH];
    __shared__ float red[64];
    int b = blockIdx.x, o = threadIdx.x;
    float acc = 0.f;
#pragma unroll
    for (int i = 0; i < K3; i++) acc += h[(size_t)(b * K3 + i) * HH + o];
    sg[o] = acc * (1.f / K3);
    __syncthreads();
    if (o < 64) {
        float a = b1[o];
        for (int i = 0; i < HH; i++) a = fmaf(sg[i], w1[i * 64 + o], a);
        a = fmaxf(a, 0.f);
        red[o] = a * w2[o];
    }
    __syncthreads();
    for (int st = 32; st > 0; st >>= 1) {
        if (o < st) red[o] += red[o + st];
        __syncthreads();
    }
    if (o == 0) out[b] = 1.f / (1.f + expf(-(red[0] + b2[0])));
}

// ---------------- host ----------------
extern "C" void kernel_launch(void* const* d_in, const int* in_sizes, int n_in,
                              void* d_out, int out_size) {
    const float* x     = (const float*)d_in[0];
    const int*   ei    = (const int*)d_in[1];
    const float* ea    = (const float*)d_in[2];
    const float* nn1_w = (const float*)d_in[4];
    const float* nn1_b = (const float*)d_in[5];
    const float* root1 = (const float*)d_in[6];
    const float* bias1 = (const float*)d_in[7];
    const float* nn2_w = (const float*)d_in[8];
    const float* nn2_b = (const float*)d_in[9];
    const float* root2 = (const float*)d_in[10];
    const float* bias2 = (const float*)d_in[11];
    const float* nn3_w = (const float*)d_in[12];
    const float* nn3_b = (const float*)d_in[13];
    const float* root3 = (const float*)d_in[14];
    const float* bias3 = (const float*)d_in[15];
    const float* gamma1 = (const float*)d_in[16];
    const float* beta1  = (const float*)d_in[17];
    const float* gamma2 = (const float*)d_in[18];
    const float* beta2  = (const float*)d_in[19];
    const float* gamma3 = (const float*)d_in[20];
    const float* beta3  = (const float*)d_in[21];
    const float* pw1 = (const float*)d_in[22];
    const float* pw2 = (const float*)d_in[23];
    const float* pw3 = (const float*)d_in[24];
    const float* l1w = (const float*)d_in[25];
    const float* l1b = (const float*)d_in[26];
    const float* l2w = (const float*)d_in[27];
    const float* l2b = (const float*)d_in[28];
    float* out = (float*)d_out;

    float *yp, *hp, *h2p, *partp;
    __nv_bfloat16 *Abp, *Bb1p, *Bb2p, *Bb3p;
    int *srcp, *dstp, *validp;
    cudaGetSymbolAddress((void**)&yp, g_y);
    cudaGetSymbolAddress((void**)&Abp, g_Ab);
    cudaGetSymbolAddress((void**)&Bb1p, g_Bb1);
    cudaGetSymbolAddress((void**)&Bb2p, g_Bb2);
    cudaGetSymbolAddress((void**)&Bb3p, g_Bb3);
    cudaGetSymbolAddress((void**)&hp, g_h);
    cudaGetSymbolAddress((void**)&h2p, g_h2);
    cudaGetSymbolAddress((void**)&partp, g_partial);
    cudaGetSymbolAddress((void**)&srcp, g_src);
    cudaGetSymbolAddress((void**)&dstp, g_dst);
    cudaGetSymbolAddress((void**)&validp, g_valid);

    cudaFuncSetAttribute(gemm_mma_k, cudaFuncAttributeMaxDynamicSharedMemorySize, GEMM_SMEM);
    const int POOL_SMEM = (NPG0 * 129 + 128 + 2 * NPG0 + 128) * 4;
    cudaFuncSetAttribute(fused_pool_k, cudaFuncAttributeMaxDynamicSharedMemorySize, POOL_SMEM);

    // ---- fused prep (edges + split_A + all split_B) ----
    prep_k<<<PREP_BLOCKS, 256>>>(ei, x, Abp,
                                 nn1_w, nn1_b, root1, Bb1p,
                                 nn2_w, nn2_b, root2, Bb2p,
                                 nn3_w, nn3_b, root3, Bb3p,
                                 srcp, dstp, validp);

    // ---- layer 1: n=4096, cin=64 ----
    gemm_mma_k<<<dim3(NDB, NN0 / 128), 256, GEMM_SMEM>>>(Abp, Bb1p, yp, bias1, h2p, CIN0);
    edge_msg_k<<<NE / 4, 128>>>(ea, yp, h2p, srcp, dstp, validp);
    bn_stats_k<<<256, HH>>>(h2p, partp, NN0);
    fused_pool_k<<<NB, HH, (NPG0 * 129 + 128 + 2 * NPG0 + 128) * 4>>>(
        h2p, partp, gamma1, beta1, pw1, hp, Abp, srcp, dstp, validp, NPG0, K1, NN0);

    // ---- layer 2: n=2048, cin=128 ----
    int n2 = NB * K1;
    gemm_mma_k<<<dim3(NDB, n2 / 128), 256, GEMM_SMEM>>>(Abp, Bb2p, yp, bias2, h2p, HH);
    edge_msg_k<<<NE / 4, 128>>>(ea, yp, h2p, srcp, dstp, validp);
    bn_stats_k<<<256, HH>>>(h2p, partp, n2);
    fused_pool_k<<<NB, HH, (K1 * 129 + 128 + 2 * K1 + 128) * 4>>>(
        h2p, partp, gamma2, beta2, pw2, hp, Abp, srcp, dstp, validp, K1, K2, n2);

    // ---- layer 3: n=1024, cin=128 ----
    int n3 = NB * K2;
    gemm_mma_k<<<dim3(NDB, n3 / 128), 256, GEMM_SMEM>>>(Abp, Bb3p, yp, bias3, h2p, HH);
    edge_msg_k<<<NE / 4, 128>>>(ea, yp, h2p, srcp, dstp, validp);
    bn_stats_k<<<256, HH>>>(h2p, partp, n3);
    fused_pool_k<<<NB, HH, (K2 * 129 + 128 + 2 * K2 + 128) * 4>>>(
        h2p, partp, gamma3, beta3, pw3, hp, Abp, srcp, dstp, validp, K2, K3, n3);

    // ---- readout ----
    readout_k<<<NB, HH>>>(hp, l1w, l1b, l2w, l2b, out);
}

// round 12
// speedup vs baseline: 1.8931x; 1.1381x over previous
#include <cuda_runtime.h>
#include <cuda_bf16.h>
#include <math.h>
#include <stdint.h>

// Problem constants
#define NB   32
#define NPG0 128
#define NE   8192
#define EPG  (NE/NB)      // 256 edges per graph (contiguous slots, valid-flagged)
#define CIN0 64
#define ED   32
#define HH   128
#define CED  33           // 32 edge-feature slices + bias slice
#define NDB  34           // + root slice (diverted to h2 in epilogue)
#define YC   (CED*HH)     // 4224 (Y stride; root slice not stored)
#define K1   64
#define K2   32
#define K3   16
#define NN0  (NB*NPG0)    // 4096

// ---------------- scratch ----------------
__device__ float g_y[NN0 * YC];                       // 69 MB
__device__ __nv_bfloat16 g_Ab[NN0 * 2 * HH];          // [h1 | h2]
__device__ __nv_bfloat16 g_Bb1[(NDB * HH) * 2 * CIN0]; // [b1 | b2]
__device__ __nv_bfloat16 g_Bb2[(NDB * HH) * 2 * HH];
__device__ __nv_bfloat16 g_Bb3[(NDB * HH) * 2 * HH];
__device__ float g_h[NN0 * HH];
__device__ float g_h2[NN0 * HH];
__device__ int   g_src[NE], g_dst[NE], g_valid[NE];
__device__ float g_partial[NB * 256];
__device__ int   g_ctr[4];                            // monotonic barrier counters

// ---------------- helpers ----------------
__device__ __forceinline__ void split2(float x, __nv_bfloat16& h1, __nv_bfloat16& h2) {
    h1 = __float2bfloat16(x);
    h2 = __float2bfloat16(x - __bfloat162float(h1));
}
__device__ __forceinline__ uint32_t smem_u32(const void* p) {
    return (uint32_t)__cvta_generic_to_shared(p);
}
__device__ __forceinline__ void cp_async16(uint32_t saddr, const void* gaddr) {
    asm volatile("cp.async.cg.shared.global [%0], [%1], 16;" :: "r"(saddr), "l"(gaddr));
}
__device__ __forceinline__ void ldsm4(uint32_t& r0, uint32_t& r1, uint32_t& r2, uint32_t& r3,
                                      uint32_t addr) {
    asm volatile("ldmatrix.sync.aligned.m8n8.x4.shared.b16 {%0,%1,%2,%3}, [%4];"
                 : "=r"(r0), "=r"(r1), "=r"(r2), "=r"(r3) : "r"(addr));
}
__device__ __forceinline__ void mma16816(float* c, const uint32_t* a, const uint32_t* b) {
    asm volatile("mma.sync.aligned.m16n8k16.row.col.f32.bf16.bf16.f32 "
                 "{%0,%1,%2,%3}, {%4,%5,%6,%7}, {%8,%9}, {%0,%1,%2,%3};"
                 : "+f"(c[0]), "+f"(c[1]), "+f"(c[2]), "+f"(c[3])
                 : "r"(a[0]), "r"(a[1]), "r"(a[2]), "r"(a[3]), "r"(b[0]), "r"(b[1]));
}

// ---------------- fused prep: init_edges + split_A(layer1) + split_B(all 3 layers) ----
__device__ __forceinline__ void split_B_elem(const float* __restrict__ W,
                                             const float* __restrict__ bvec,
                                             const float* __restrict__ root,
                                             __nv_bfloat16* __restrict__ Bb,
                                             int i, int cin) {
    int t = i / cin, k = i - t * cin;
    int d = t >> 7, o = t & 127;
    float w;
    if (d < ED)       w = W[(size_t)(d * cin + k) * HH + o];
    else if (d == ED) w = bvec[(size_t)k * HH + o];
    else              w = root[(size_t)k * HH + o];
    __nv_bfloat16 b1, b2;
    split2(w, b1, b2);
    __nv_bfloat16* row = Bb + (size_t)t * 2 * cin + k;
    row[0] = b1; row[cin] = b2;
}

#define PREP_SEG0 32      // init_edges: 8192 / 256
#define PREP_SEG1 1024    // split_A layer1: 4096*64 / 256
#define PREP_SEG2 1088    // split_B1: 34*128*64 / 256
#define PREP_SEG3 2176    // split_B2: 34*128*128 / 256
#define PREP_SEG4 2176    // split_B3
#define PREP_BLOCKS (PREP_SEG0 + PREP_SEG1 + PREP_SEG2 + PREP_SEG3 + PREP_SEG4)

__global__ void prep_k(const int* __restrict__ ei, const float* __restrict__ x,
                       __nv_bfloat16* __restrict__ Ab,
                       const float* __restrict__ nn1_w, const float* __restrict__ nn1_b,
                       const float* __restrict__ root1, __nv_bfloat16* __restrict__ Bb1,
                       const float* __restrict__ nn2_w, const float* __restrict__ nn2_b,
                       const float* __restrict__ root2, __nv_bfloat16* __restrict__ Bb2,
                       const float* __restrict__ nn3_w, const float* __restrict__ nn3_b,
                       const float* __restrict__ root3, __nv_bfloat16* __restrict__ Bb3,
                       int* __restrict__ src, int* __restrict__ dst,
                       int* __restrict__ valid) {
    int blk = blockIdx.x;
    if (blk < PREP_SEG0) {
        int e = blk * 256 + threadIdx.x;
        src[e] = ei[e]; dst[e] = ei[NE + e]; valid[e] = 1;
        return;
    }
    blk -= PREP_SEG0;
    if (blk < PREP_SEG1) {
        int i = blk * 256 + threadIdx.x;          // < 4096*64
        int r = i >> 6, k = i & 63;
        __nv_bfloat16 h1, h2;
        split2(x[i], h1, h2);
        __nv_bfloat16* row = Ab + (size_t)r * 2 * CIN0 + k;
        row[0] = h1; row[CIN0] = h2;
        return;
    }
    blk -= PREP_SEG1;
    if (blk < PREP_SEG2) {
        split_B_elem(nn1_w, nn1_b, root1, Bb1, blk * 256 + threadIdx.x, CIN0);
        return;
    }
    blk -= PREP_SEG2;
    if (blk < PREP_SEG3) {
        split_B_elem(nn2_w, nn2_b, root2, Bb2, blk * 256 + threadIdx.x, HH);
        return;
    }
    blk -= PREP_SEG3;
    split_B_elem(nn3_w, nn3_b, root3, Bb3, blk * 256 + threadIdx.x, HH);
}

// ---------------- raw mma.sync GEMM with A/B register-reuse over split pairs -------
// (R11 mainloop, unchanged: 2/3-traffic 3-term split, fixed ring schedule)
#define SROW 72                // 64+8 bf16 per row slot (144B)
#define STG  (128 * SROW)      // elems per matrix per stage
#define GEMM_SMEM (3 * 2 * STG * 2)   // 110592 bytes, 3 stages

__global__ __launch_bounds__(256, 2)
void gemm_mma_k(const __nv_bfloat16* __restrict__ Ab, const __nv_bfloat16* __restrict__ Bb,
                float* __restrict__ Y, const float* __restrict__ bias,
                float* __restrict__ h2agg, int cin) {
    extern __shared__ __nv_bfloat16 sm[];
    const int tid = threadIdx.x;
    const int lane = tid & 31;
    const int wid = tid >> 5;
    const int warp_m = wid & 3;     // 0..3 -> 32-row slice
    const int warp_n = wid >> 2;    // 0..1 -> 64-col slice
    const int mbase = blockIdx.y * 128;
    const int nbase = blockIdx.x * 128;
    const int Kp2 = 2 * cin;
    const int NPAIR = cin >> 6;
    const int NCH = NPAIR * 2;

    float acc[2][8][4];
#pragma unroll
    for (int i = 0; i < 2; i++)
#pragma unroll
        for (int j = 0; j < 8; j++)
#pragma unroll
            for (int q = 0; q < 4; q++) acc[i][j][q] = 0.f;

    auto prefetch = [&](int c) {
        const int s = c % 3;
        const int kc = (c & 1) * cin + ((c >> 1) << 6);
        __nv_bfloat16* base = sm + s * 2 * STG;
#pragma unroll
        for (int u = 0; u < 8; u++) {
            int q = tid + u * 256;            // 0..2047
            int isB = q >> 10;
            int qq = q & 1023;
            int r = qq >> 3, ch = qq & 7;
            const __nv_bfloat16* g = isB
                ? (Bb + (size_t)(nbase + r) * Kp2 + kc + ch * 8)
                : (Ab + (size_t)(mbase + r) * Kp2 + kc + ch * 8);
            cp_async16(smem_u32(base + isB * STG + r * SROW + ch * 8), g);
        }
        asm volatile("cp.async.commit_group;" ::: "memory");
    };

    prefetch(0);
    prefetch(1);
    if (NCH > 2) prefetch(2);

    for (int p = 0; p < NPAIR; p++) {
        if (2 * p + 2 < NCH) asm volatile("cp.async.wait_group 1;" ::: "memory");
        else                 asm volatile("cp.async.wait_group 0;" ::: "memory");
        __syncthreads();

        const int sA = (2 * p) % 3, sB = (2 * p + 1) % 3;
        const uint32_t a1_base = smem_u32(sm + sA * 2 * STG);
        const uint32_t b1_base = a1_base + STG * 2;
        const uint32_t a2_base = smem_u32(sm + sB * 2 * STG);
        const uint32_t b2_base = a2_base + STG * 2;

        const int m8 = lane >> 3;
        const int arow_off = warp_m * 32 + (lane & 15);
        const int acol_sel = (lane >> 4) * 8;
        const int brow0 = warp_n * 64 + (m8 >> 1) * 8 + (lane & 7);
        const int bcol_sel = (m8 & 1) * 8;

#pragma unroll
        for (int kk = 0; kk < 4; kk++) {
            const uint32_t aoff = (uint32_t)(kk * 16 + acol_sel) * 2;
            const uint32_t boff = (uint32_t)(kk * 16 + bcol_sel) * 2;

            uint32_t af1[2][4];
#pragma unroll
            for (int i = 0; i < 2; i++)
                ldsm4(af1[i][0], af1[i][1], af1[i][2], af1[i][3],
                      a1_base + (uint32_t)((arow_off + i * 16) * SROW) * 2 + aoff);
            uint32_t bf1[8][2];
#pragma unroll
            for (int g = 0; g < 4; g++)
                ldsm4(bf1[2 * g][0], bf1[2 * g][1], bf1[2 * g + 1][0], bf1[2 * g + 1][1],
                      b1_base + (uint32_t)((brow0 + g * 16) * SROW) * 2 + boff);
#pragma unroll
            for (int i = 0; i < 2; i++)
#pragma unroll
                for (int j = 0; j < 8; j++)
                    mma16816(acc[i][j], af1[i], bf1[j]);

            uint32_t af2[2][4];
#pragma unroll
            for (int i = 0; i < 2; i++)
                ldsm4(af2[i][0], af2[i][1], af2[i][2], af2[i][3],
                      a2_base + (uint32_t)((arow_off + i * 16) * SROW) * 2 + aoff);
#pragma unroll
            for (int i = 0; i < 2; i++)
#pragma unroll
                for (int j = 0; j < 8; j++)
                    mma16816(acc[i][j], af2[i], bf1[j]);

            uint32_t bf2[8][2];
#pragma unroll
            for (int g = 0; g < 4; g++)
                ldsm4(bf2[2 * g][0], bf2[2 * g][1], bf2[2 * g + 1][0], bf2[2 * g + 1][1],
                      b2_base + (uint32_t)((brow0 + g * 16) * SROW) * 2 + boff);
#pragma unroll
            for (int i = 0; i < 2; i++)
#pragma unroll
                for (int j = 0; j < 8; j++)
                    mma16816(acc[i][j], af1[i], bf2[j]);
        }

        if (2 * p + 3 < NCH) {
            __syncthreads();
            prefetch(2 * p + 3);
        }
    }

    // epilogue
    const int gid = lane >> 2, tig = lane & 3;
    if (blockIdx.x == 33) {
#pragma unroll
        for (int i = 0; i < 2; i++) {
            int row = mbase + warp_m * 32 + i * 16 + gid;
#pragma unroll
            for (int j = 0; j < 8; j++) {
                int col = warp_n * 64 + j * 8 + tig * 2;
                float b0 = bias[col], b1 = bias[col + 1];
                float* d0 = h2agg + (size_t)row * HH + col;
                d0[0] = acc[i][j][0] + b0;
                d0[1] = acc[i][j][1] + b1;
                float* d1 = h2agg + (size_t)(row + 8) * HH + col;
                d1[0] = acc[i][j][2] + b0;
                d1[1] = acc[i][j][3] + b1;
            }
        }
    } else {
#pragma unroll
        for (int i = 0; i < 2; i++) {
            int row = mbase + warp_m * 32 + i * 16 + gid;
#pragma unroll
            for (int j = 0; j < 8; j++) {
                int col = nbase + warp_n * 64 + j * 8 + tig * 2;
                *reinterpret_cast<float2*>(Y + (size_t)row * YC + col) =
                    make_float2(acc[i][j][0], acc[i][j][1]);
                *reinterpret_cast<float2*>(Y + (size_t)(row + 8) * YC + col) =
                    make_float2(acc[i][j][2], acc[i][j][3]);
            }
        }
    }
}

// ---------------- pipeline kernels ----------------
// warp-per-edge, float4 lanes, coefficients via shuffle
__global__ void edge_msg_k(const float* __restrict__ ea, const float* __restrict__ y,
                           float* __restrict__ agg, const int* __restrict__ src,
                           const int* __restrict__ dst, const int* __restrict__ valid) {
    int e = blockIdx.x * 4 + (threadIdx.x >> 5);
    int lane = threadIdx.x & 31;
    if (!valid[e]) return;
    float av = ea[(size_t)e * ED + lane];
    const float4* yr = reinterpret_cast<const float4*>(y + (size_t)src[e] * YC) + lane;
    float4 acc = make_float4(0.f, 0.f, 0.f, 0.f);
#pragma unroll
    for (int d = 0; d < ED; d++) {
        float ad = __shfl_sync(0xffffffffu, av, d);
        float4 v = yr[d * 32];
        acc.x = fmaf(ad, v.x, acc.x);
        acc.y = fmaf(ad, v.y, acc.y);
        acc.z = fmaf(ad, v.z, acc.z);
        acc.w = fmaf(ad, v.w, acc.w);
    }
    {
        float4 v = yr[ED * 32];
        acc.x += v.x; acc.y += v.y; acc.z += v.z; acc.w += v.w;
    }
    float* ag = agg + (size_t)dst[e] * HH + lane * 4;
    atomicAdd(ag + 0, acc.x);
    atomicAdd(ag + 1, acc.y);
    atomicAdd(ag + 2, acc.z);
    atomicAdd(ag + 3, acc.w);
}

// fused: BN stats (grid barrier) + BN apply + ReLU + score + topk + gather(+scale)
//        + split-A + edge remap. 32 blocks (one per graph), all co-resident.
__global__ void fused_pool_k(const float* __restrict__ h2, float* __restrict__ partial,
                             int* __restrict__ ctr,
                             const float* __restrict__ gamma, const float* __restrict__ beta,
                             const float* __restrict__ pw,
                             float* __restrict__ hout, __nv_bfloat16* __restrict__ Ab,
                             int* __restrict__ src, int* __restrict__ dst,
                             int* __restrict__ valid,
                             int npg, int kk, int n) {
    extern __shared__ float fs[];
    float* tile = fs;                       // npg * 129
    float* spw  = tile + npg * 129;         // 128
    float* sc   = spw + 128;                // npg
    float* red  = sc + npg;                 // 128
    int*   rankA = (int*)(red + 128);       // npg

    const int b = blockIdx.x, o = threadIdx.x;
    const int base = b * npg;

    // load raw h2 into tile + per-graph channel partials
    float s = 0.f, s2 = 0.f;
    for (int i = 0; i < npg; i++) {
        float v = h2[(size_t)(base + i) * HH + o];
        tile[i * 129 + o] = v;
        s += v; s2 += v * v;
    }
    partial[b * 256 + o] = s;
    partial[b * 256 + 128 + o] = s2;
    __threadfence();
    __syncthreads();                         // all partials of this block published
    if (o == 0) {
        int old = atomicAdd(ctr, 1);
        int target = ((old >> 5) << 5) + 32; // this launch's window (monotonic, no reset)
        while (*(volatile int*)ctr < target) {}
    }
    __syncthreads();
    __threadfence();

    float S = 0.f, S2 = 0.f;
#pragma unroll 8
    for (int j = 0; j < NB; j++) {
        S  += __ldcg(&partial[j * 256 + o]);
        S2 += __ldcg(&partial[j * 256 + 128 + o]);
    }
    float inv_n = 1.f / (float)n;
    float mu = S * inv_n;
    float var = S2 * inv_n - mu * mu;
    float scal = gamma[o] * rsqrtf(var + 1e-5f);
    float be = beta[o];

    float pwo = pw[o];
    spw[o] = pwo;
    red[o] = pwo * pwo;
    __syncthreads();
    for (int st = 64; st > 0; st >>= 1) {
        if (o < st) red[o] += red[o + st];
        __syncthreads();
    }
    float pwn = sqrtf(red[0]);

    // BN + ReLU in place
    for (int i = 0; i < npg; i++) {
        tile[i * 129 + o] = fmaxf(scal * (tile[i * 129 + o] - mu) + be, 0.f);
    }
    __syncthreads();

    if (o < npg) {
        float acc = 0.f;
#pragma unroll 16
        for (int c = 0; c < HH; c++) acc += tile[o * 129 + c] * spw[c];
        sc[o] = tanhf(acc / pwn);
    }
    __syncthreads();

    if (o < npg) {
        float mine = sc[o];
        int r = 0;
        for (int j = 0; j < npg; j++) {
            float sj = sc[j];
            r += (sj > mine) || (sj == mine && j < o);
        }
        rankA[o] = r;
    }
    __syncthreads();

    for (int i = 0; i < npg; i++) {
        int r = rankA[i];
        if (r < kk) {
            int nid = b * kk + r;
            float val = tile[i * 129 + o] * sc[i];
            hout[(size_t)nid * HH + o] = val;
            __nv_bfloat16 h1, h2b;
            split2(val, h1, h2b);
            __nv_bfloat16* row = Ab + (size_t)nid * (2 * HH) + o;
            row[0] = h1; row[HH] = h2b;
        }
    }

    for (int e = b * EPG + o; e < (b + 1) * EPG; e += 128) {
        if (valid[e]) {
            int rs = rankA[src[e] - base];
            int rd = rankA[dst[e] - base];
            if (rs < kk && rd < kk) { src[e] = b * kk + rs; dst[e] = b * kk + rd; }
            else valid[e] = 0;
        }
    }
}

// fused meanpool + 2-layer MLP + sigmoid
__global__ void readout_k(const float* __restrict__ h, const float* __restrict__ w1,
                          const float* __restrict__ b1, const float* __restrict__ w2,
                          const float* __restrict__ b2, float* __restrict__ out) {
    __shared__ float sg[HH];
    __shared__ float red[64];
    int b = blockIdx.x, o = threadIdx.x;
    float acc = 0.f;
#pragma unroll
    for (int i = 0; i < K3; i++) acc += h[(size_t)(b * K3 + i) * HH + o];
    sg[o] = acc * (1.f / K3);
    __syncthreads();
    if (o < 64) {
        float a = b1[o];
        for (int i = 0; i < HH; i++) a = fmaf(sg[i], w1[i * 64 + o], a);
        a = fmaxf(a, 0.f);
        red[o] = a * w2[o];
    }
    __syncthreads();
    for (int st = 32; st > 0; st >>= 1) {
        if (o < st) red[o] += red[o + st];
        __syncthreads();
    }
    if (o == 0) out[b] = 1.f / (1.f + expf(-(red[0] + b2[0])));
}

// ---------------- host ----------------
extern "C" void kernel_launch(void* const* d_in, const int* in_sizes, int n_in,
                              void* d_out, int out_size) {
    const float* x     = (const float*)d_in[0];
    const int*   ei    = (const int*)d_in[1];
    const float* ea    = (const float*)d_in[2];
    const float* nn1_w = (const float*)d_in[4];
    const float* nn1_b = (const float*)d_in[5];
    const float* root1 = (const float*)d_in[6];
    const float* bias1 = (const float*)d_in[7];
    const float* nn2_w = (const float*)d_in[8];
    const float* nn2_b = (const float*)d_in[9];
    const float* root2 = (const float*)d_in[10];
    const float* bias2 = (const float*)d_in[11];
    const float* nn3_w = (const float*)d_in[12];
    const float* nn3_b = (const float*)d_in[13];
    const float* root3 = (const float*)d_in[14];
    const float* bias3 = (const float*)d_in[15];
    const float* gamma1 = (const float*)d_in[16];
    const float* beta1  = (const float*)d_in[17];
    const float* gamma2 = (const float*)d_in[18];
    const float* beta2  = (const float*)d_in[19];
    const float* gamma3 = (const float*)d_in[20];
    const float* beta3  = (const float*)d_in[21];
    const float* pw1 = (const float*)d_in[22];
    const float* pw2 = (const float*)d_in[23];
    const float* pw3 = (const float*)d_in[24];
    const float* l1w = (const float*)d_in[25];
    const float* l1b = (const float*)d_in[26];
    const float* l2w = (const float*)d_in[27];
    const float* l2b = (const float*)d_in[28];
    float* out = (float*)d_out;

    float *yp, *hp, *h2p, *partp;
    __nv_bfloat16 *Abp, *Bb1p, *Bb2p, *Bb3p;
    int *srcp, *dstp, *validp, *ctrp;
    cudaGetSymbolAddress((void**)&yp, g_y);
    cudaGetSymbolAddress((void**)&Abp, g_Ab);
    cudaGetSymbolAddress((void**)&Bb1p, g_Bb1);
    cudaGetSymbolAddress((void**)&Bb2p, g_Bb2);
    cudaGetSymbolAddress((void**)&Bb3p, g_Bb3);
    cudaGetSymbolAddress((void**)&hp, g_h);
    cudaGetSymbolAddress((void**)&h2p, g_h2);
    cudaGetSymbolAddress((void**)&partp, g_partial);
    cudaGetSymbolAddress((void**)&srcp, g_src);
    cudaGetSymbolAddress((void**)&dstp, g_dst);
    cudaGetSymbolAddress((void**)&validp, g_valid);
    cudaGetSymbolAddress((void**)&ctrp, g_ctr);

    cudaFuncSetAttribute(gemm_mma_k, cudaFuncAttributeMaxDynamicSharedMemorySize, GEMM_SMEM);
    const int POOL_SMEM = (NPG0 * 129 + 128 + 2 * NPG0 + 128) * 4;
    cudaFuncSetAttribute(fused_pool_k, cudaFuncAttributeMaxDynamicSharedMemorySize, POOL_SMEM);

    // ---- fused prep (edges + split_A + all split_B) ----
    prep_k<<<PREP_BLOCKS, 256>>>(ei, x, Abp,
                                 nn1_w, nn1_b, root1, Bb1p,
                                 nn2_w, nn2_b, root2, Bb2p,
                                 nn3_w, nn3_b, root3, Bb3p,
                                 srcp, dstp, validp);

    // ---- layer 1: n=4096, cin=64 ----
    gemm_mma_k<<<dim3(NDB, NN0 / 128), 256, GEMM_SMEM>>>(Abp, Bb1p, yp, bias1, h2p, CIN0);
    edge_msg_k<<<NE / 4, 128>>>(ea, yp, h2p, srcp, dstp, validp);
    fused_pool_k<<<NB, HH, (NPG0 * 129 + 128 + 2 * NPG0 + 128) * 4>>>(
        h2p, partp, ctrp + 0, gamma1, beta1, pw1, hp, Abp, srcp, dstp, validp,
        NPG0, K1, NN0);

    // ---- layer 2: n=2048, cin=128 ----
    int n2 = NB * K1;
    gemm_mma_k<<<dim3(NDB, n2 / 128), 256, GEMM_SMEM>>>(Abp, Bb2p, yp, bias2, h2p, HH);
    edge_msg_k<<<NE / 4, 128>>>(ea, yp, h2p, srcp, dstp, validp);
    fused_pool_k<<<NB, HH, (K1 * 129 + 128 + 2 * K1 + 128) * 4>>>(
        h2p, partp, ctrp + 1, gamma2, beta2, pw2, hp, Abp, srcp, dstp, validp,
        K1, K2, n2);

    // ---- layer 3: n=1024, cin=128 ----
    int n3 = NB * K2;
    gemm_mma_k<<<dim3(NDB, n3 / 128), 256, GEMM_SMEM>>>(Abp, Bb3p, yp, bias3, h2p, HH);
    edge_msg_k<<<NE / 4, 128>>>(ea, yp, h2p, srcp, dstp, validp);
    fused_pool_k<<<NB, HH, (K2 * 129 + 128 + 2 * K2 + 128) * 4>>>(
        h2p, partp, ctrp + 2, gamma3, beta3, pw3, hp, Abp, srcp, dstp, validp,
        K2, K3, n3);

    // ---- readout ----
    readout_k<<<NB, HH>>>(hp, l1w, l1b, l2w, l2b, out);
}

// round 14
// speedup vs baseline: 1.9833x; 1.0476x over previous
#include <cuda_runtime.h>
#include <cuda_bf16.h>
#include <math.h>
#include <stdint.h>

// Problem constants
#define NB   32
#define NPG0 128
#define NE   8192
#define EPG  (NE/NB)      // 256 edges per graph (contiguous slots, valid-flagged)
#define CIN0 64
#define ED   32
#define HH   128
#define CED  33           // 32 edge-feature slices + bias slice
#define NDB  34           // + root slice (diverted to h2 in epilogue)
#define YC   (CED*HH)     // 4224 (Y stride; root slice not stored)
#define K1   64
#define K2   32
#define K3   16
#define NN0  (NB*NPG0)    // 4096

// ---------------- scratch ----------------
__device__ float g_y[NN0 * YC];                       // 69 MB
__device__ __nv_bfloat16 g_Ab[NN0 * 2 * HH];          // [h1 | h2]
__device__ __nv_bfloat16 g_Bb1[(NDB * HH) * 2 * CIN0]; // [b1 | b2]
__device__ __nv_bfloat16 g_Bb2[(NDB * HH) * 2 * HH];
__device__ __nv_bfloat16 g_Bb3[(NDB * HH) * 2 * HH];
__device__ float g_h[NN0 * HH];
__device__ float g_h2[NN0 * HH];
__device__ int   g_src[NE], g_dst[NE], g_valid[NE];
__device__ float g_partial[NB * 256];
__device__ int   g_ctr[4];                            // monotonic barrier counters

// ---------------- helpers ----------------
__device__ __forceinline__ void split2(float x, __nv_bfloat16& h1, __nv_bfloat16& h2) {
    h1 = __float2bfloat16(x);
    h2 = __float2bfloat16(x - __bfloat162float(h1));
}
__device__ __forceinline__ uint32_t smem_u32(const void* p) {
    return (uint32_t)__cvta_generic_to_shared(p);
}
__device__ __forceinline__ void cp_async16(uint32_t saddr, const void* gaddr) {
    asm volatile("cp.async.cg.shared.global [%0], [%1], 16;" :: "r"(saddr), "l"(gaddr));
}
__device__ __forceinline__ void ldsm4(uint32_t& r0, uint32_t& r1, uint32_t& r2, uint32_t& r3,
                                      uint32_t addr) {
    asm volatile("ldmatrix.sync.aligned.m8n8.x4.shared.b16 {%0,%1,%2,%3}, [%4];"
                 : "=r"(r0), "=r"(r1), "=r"(r2), "=r"(r3) : "r"(addr));
}
__device__ __forceinline__ void mma16816(float* c, const uint32_t* a, const uint32_t* b) {
    asm volatile("mma.sync.aligned.m16n8k16.row.col.f32.bf16.bf16.f32 "
                 "{%0,%1,%2,%3}, {%4,%5,%6,%7}, {%8,%9}, {%0,%1,%2,%3};"
                 : "+f"(c[0]), "+f"(c[1]), "+f"(c[2]), "+f"(c[3])
                 : "r"(a[0]), "r"(a[1]), "r"(a[2]), "r"(a[3]), "r"(b[0]), "r"(b[1]));
}

// ---------------- fused prep: init_edges + split_A(layer1) + split_B(all 3 layers) ----
__device__ __forceinline__ void split_B_elem(const float* __restrict__ W,
                                             const float* __restrict__ bvec,
                                             const float* __restrict__ root,
                                             __nv_bfloat16* __restrict__ Bb,
                                             int i, int cin) {
    int t = i / cin, k = i - t * cin;
    int d = t >> 7, o = t & 127;
    float w;
    if (d < ED)       w = W[(size_t)(d * cin + k) * HH + o];
    else if (d == ED) w = bvec[(size_t)k * HH + o];
    else              w = root[(size_t)k * HH + o];
    __nv_bfloat16 b1, b2;
    split2(w, b1, b2);
    __nv_bfloat16* row = Bb + (size_t)t * 2 * cin + k;
    row[0] = b1; row[cin] = b2;
}

#define PREP_SEG0 32      // init_edges: 8192 / 256
#define PREP_SEG1 1024    // split_A layer1: 4096*64 / 256
#define PREP_SEG2 1088    // split_B1: 34*128*64 / 256
#define PREP_SEG3 2176    // split_B2: 34*128*128 / 256
#define PREP_SEG4 2176    // split_B3
#define PREP_BLOCKS (PREP_SEG0 + PREP_SEG1 + PREP_SEG2 + PREP_SEG3 + PREP_SEG4)

__global__ void prep_k(const int* __restrict__ ei, const float* __restrict__ x,
                       __nv_bfloat16* __restrict__ Ab,
                       const float* __restrict__ nn1_w, const float* __restrict__ nn1_b,
                       const float* __restrict__ root1, __nv_bfloat16* __restrict__ Bb1,
                       const float* __restrict__ nn2_w, const float* __restrict__ nn2_b,
                       const float* __restrict__ root2, __nv_bfloat16* __restrict__ Bb2,
                       const float* __restrict__ nn3_w, const float* __restrict__ nn3_b,
                       const float* __restrict__ root3, __nv_bfloat16* __restrict__ Bb3,
                       int* __restrict__ src, int* __restrict__ dst,
                       int* __restrict__ valid) {
    int blk = blockIdx.x;
    if (blk < PREP_SEG0) {
        int e = blk * 256 + threadIdx.x;
        src[e] = ei[e]; dst[e] = ei[NE + e]; valid[e] = 1;
        return;
    }
    blk -= PREP_SEG0;
    if (blk < PREP_SEG1) {
        int i = blk * 256 + threadIdx.x;          // < 4096*64
        int r = i >> 6, k = i & 63;
        __nv_bfloat16 h1, h2;
        split2(x[i], h1, h2);
        __nv_bfloat16* row = Ab + (size_t)r * 2 * CIN0 + k;
        row[0] = h1; row[CIN0] = h2;
        return;
    }
    blk -= PREP_SEG1;
    if (blk < PREP_SEG2) {
        split_B_elem(nn1_w, nn1_b, root1, Bb1, blk * 256 + threadIdx.x, CIN0);
        return;
    }
    blk -= PREP_SEG2;
    if (blk < PREP_SEG3) {
        split_B_elem(nn2_w, nn2_b, root2, Bb2, blk * 256 + threadIdx.x, HH);
        return;
    }
    blk -= PREP_SEG3;
    split_B_elem(nn3_w, nn3_b, root3, Bb3, blk * 256 + threadIdx.x, HH);
}

// ---------------- raw mma.sync GEMM (R11 mainloop, unchanged) ----------------
#define SROW 72                // 64+8 bf16 per row slot (144B)
#define STG  (128 * SROW)      // elems per matrix per stage
#define GEMM_SMEM (3 * 2 * STG * 2)   // 110592 bytes, 3 stages

__global__ __launch_bounds__(256, 2)
void gemm_mma_k(const __nv_bfloat16* __restrict__ Ab, const __nv_bfloat16* __restrict__ Bb,
                float* __restrict__ Y, const float* __restrict__ bias,
                float* __restrict__ h2agg, int cin) {
    extern __shared__ __nv_bfloat16 sm[];
    const int tid = threadIdx.x;
    const int lane = tid & 31;
    const int wid = tid >> 5;
    const int warp_m = wid & 3;
    const int warp_n = wid >> 2;
    const int mbase = blockIdx.y * 128;
    const int nbase = blockIdx.x * 128;
    const int Kp2 = 2 * cin;
    const int NPAIR = cin >> 6;
    const int NCH = NPAIR * 2;

    float acc[2][8][4];
#pragma unroll
    for (int i = 0; i < 2; i++)
#pragma unroll
        for (int j = 0; j < 8; j++)
#pragma unroll
            for (int q = 0; q < 4; q++) acc[i][j][q] = 0.f;

    auto prefetch = [&](int c) {
        const int s = c % 3;
        const int kc = (c & 1) * cin + ((c >> 1) << 6);
        __nv_bfloat16* base = sm + s * 2 * STG;
#pragma unroll
        for (int u = 0; u < 8; u++) {
            int q = tid + u * 256;
            int isB = q >> 10;
            int qq = q & 1023;
            int r = qq >> 3, ch = qq & 7;
            const __nv_bfloat16* g = isB
                ? (Bb + (size_t)(nbase + r) * Kp2 + kc + ch * 8)
                : (Ab + (size_t)(mbase + r) * Kp2 + kc + ch * 8);
            cp_async16(smem_u32(base + isB * STG + r * SROW + ch * 8), g);
        }
        asm volatile("cp.async.commit_group;" ::: "memory");
    };

    prefetch(0);
    prefetch(1);
    if (NCH > 2) prefetch(2);

    for (int p = 0; p < NPAIR; p++) {
        if (2 * p + 2 < NCH) asm volatile("cp.async.wait_group 1;" ::: "memory");
        else                 asm volatile("cp.async.wait_group 0;" ::: "memory");
        __syncthreads();

        const int sA = (2 * p) % 3, sB = (2 * p + 1) % 3;
        const uint32_t a1_base = smem_u32(sm + sA * 2 * STG);
        const uint32_t b1_base = a1_base + STG * 2;
        const uint32_t a2_base = smem_u32(sm + sB * 2 * STG);
        const uint32_t b2_base = a2_base + STG * 2;

        const int m8 = lane >> 3;
        const int arow_off = warp_m * 32 + (lane & 15);
        const int acol_sel = (lane >> 4) * 8;
        const int brow0 = warp_n * 64 + (m8 >> 1) * 8 + (lane & 7);
        const int bcol_sel = (m8 & 1) * 8;

#pragma unroll
        for (int kk = 0; kk < 4; kk++) {
            const uint32_t aoff = (uint32_t)(kk * 16 + acol_sel) * 2;
            const uint32_t boff = (uint32_t)(kk * 16 + bcol_sel) * 2;

            uint32_t af1[2][4];
#pragma unroll
            for (int i = 0; i < 2; i++)
                ldsm4(af1[i][0], af1[i][1], af1[i][2], af1[i][3],
                      a1_base + (uint32_t)((arow_off + i * 16) * SROW) * 2 + aoff);
            uint32_t bf1[8][2];
#pragma unroll
            for (int g = 0; g < 4; g++)
                ldsm4(bf1[2 * g][0], bf1[2 * g][1], bf1[2 * g + 1][0], bf1[2 * g + 1][1],
                      b1_base + (uint32_t)((brow0 + g * 16) * SROW) * 2 + boff);
#pragma unroll
            for (int i = 0; i < 2; i++)
#pragma unroll
                for (int j = 0; j < 8; j++)
                    mma16816(acc[i][j], af1[i], bf1[j]);

            uint32_t af2[2][4];
#pragma unroll
            for (int i = 0; i < 2; i++)
                ldsm4(af2[i][0], af2[i][1], af2[i][2], af2[i][3],
                      a2_base + (uint32_t)((arow_off + i * 16) * SROW) * 2 + aoff);
#pragma unroll
            for (int i = 0; i < 2; i++)
#pragma unroll
                for (int j = 0; j < 8; j++)
                    mma16816(acc[i][j], af2[i], bf1[j]);

            uint32_t bf2[8][2];
#pragma unroll
            for (int g = 0; g < 4; g++)
                ldsm4(bf2[2 * g][0], bf2[2 * g][1], bf2[2 * g + 1][0], bf2[2 * g + 1][1],
                      b2_base + (uint32_t)((brow0 + g * 16) * SROW) * 2 + boff);
#pragma unroll
            for (int i = 0; i < 2; i++)
#pragma unroll
                for (int j = 0; j < 8; j++)
                    mma16816(acc[i][j], af1[i], bf2[j]);
        }

        if (2 * p + 3 < NCH) {
            __syncthreads();
            prefetch(2 * p + 3);
        }
    }

    // epilogue
    const int gid = lane >> 2, tig = lane & 3;
    if (blockIdx.x == 33) {
#pragma unroll
        for (int i = 0; i < 2; i++) {
            int row = mbase + warp_m * 32 + i * 16 + gid;
#pragma unroll
            for (int j = 0; j < 8; j++) {
                int col = warp_n * 64 + j * 8 + tig * 2;
                float b0 = bias[col], b1 = bias[col + 1];
                float* d0 = h2agg + (size_t)row * HH + col;
                d0[0] = acc[i][j][0] + b0;
                d0[1] = acc[i][j][1] + b1;
                float* d1 = h2agg + (size_t)(row + 8) * HH + col;
                d1[0] = acc[i][j][2] + b0;
                d1[1] = acc[i][j][3] + b1;
            }
        }
    } else {
#pragma unroll
        for (int i = 0; i < 2; i++) {
            int row = mbase + warp_m * 32 + i * 16 + gid;
#pragma unroll
            for (int j = 0; j < 8; j++) {
                int col = nbase + warp_n * 64 + j * 8 + tig * 2;
                *reinterpret_cast<float2*>(Y + (size_t)row * YC + col) =
                    make_float2(acc[i][j][0], acc[i][j][1]);
                *reinterpret_cast<float2*>(Y + (size_t)(row + 8) * YC + col) =
                    make_float2(acc[i][j][2], acc[i][j][3]);
            }
        }
    }
}

// ---------------- pipeline kernels ----------------
__global__ void edge_msg_k(const float* __restrict__ ea, const float* __restrict__ y,
                           float* __restrict__ agg, const int* __restrict__ src,
                           const int* __restrict__ dst, const int* __restrict__ valid) {
    int e = blockIdx.x * 4 + (threadIdx.x >> 5);
    int lane = threadIdx.x & 31;
    if (!valid[e]) return;
    float av = ea[(size_t)e * ED + lane];
    const float4* yr = reinterpret_cast<const float4*>(y + (size_t)src[e] * YC) + lane;
    float4 acc = make_float4(0.f, 0.f, 0.f, 0.f);
#pragma unroll
    for (int d = 0; d < ED; d++) {
        float ad = __shfl_sync(0xffffffffu, av, d);
        float4 v = yr[d * 32];
        acc.x = fmaf(ad, v.x, acc.x);
        acc.y = fmaf(ad, v.y, acc.y);
        acc.z = fmaf(ad, v.z, acc.z);
        acc.w = fmaf(ad, v.w, acc.w);
    }
    {
        float4 v = yr[ED * 32];
        acc.x += v.x; acc.y += v.y; acc.z += v.z; acc.w += v.w;
    }
    float* ag = agg + (size_t)dst[e] * HH + lane * 4;
    atomicAdd(ag + 0, acc.x);
    atomicAdd(ag + 1, acc.y);
    atomicAdd(ag + 2, acc.z);
    atomicAdd(ag + 3, acc.w);
}

// fused pool, 512 threads: BN stats (grid barrier) + BN apply + ReLU + score (warp-coop)
// + topk (warp-coop) + gather(+scale) + split-A + edge remap. 32 blocks co-resident.
#define POOL_NT 512

__global__ __launch_bounds__(POOL_NT, 1)
void fused_pool_k(const float* __restrict__ h2, float* __restrict__ partial,
                  int* __restrict__ ctr,
                  const float* __restrict__ gamma, const float* __restrict__ beta,
                  const float* __restrict__ pw,
                  float* __restrict__ hout, __nv_bfloat16* __restrict__ Ab,
                  int* __restrict__ src, int* __restrict__ dst,
                  int* __restrict__ valid,
                  int npg, int kk, int n) {
    extern __shared__ float fs[];
    float* tile = fs;                        // npg * 129
    float* spw  = tile + npg * 129;          // 128
    float* sc   = spw + 128;                 // npg
    float* gred  = sc + npg;                 // 512 (per-group channel sums)
    float* gred2 = gred + 512;               // 512
    int*   rankA = (int*)(gred2 + 512);      // npg

    const int b = blockIdx.x;
    const int tid = threadIdx.x;             // 0..511
    const int lane = tid & 31;
    const int o = tid & 127;                 // channel
    const int g4 = tid >> 7;                 // 0..3 row group
    const int base = b * npg;

    // load raw h2 into tile (4-way row parallel) + group partials
    float s = 0.f, s2 = 0.f;
    for (int i = g4; i < npg; i += 4) {
        float v = h2[(size_t)(base + i) * HH + o];
        tile[i * 129 + o] = v;
        s += v; s2 += v * v;
    }
    gred[g4 * 128 + o] = s;
    gred2[g4 * 128 + o] = s2;
    if (tid < 128) spw[tid] = pw[tid];
    __syncthreads();
    if (g4 == 0) {
        float ss  = gred[o] + gred[128 + o] + gred[256 + o] + gred[384 + o];
        float ss2 = gred2[o] + gred2[128 + o] + gred2[256 + o] + gred2[384 + o];
        partial[b * 256 + o] = ss;
        partial[b * 256 + 128 + o] = ss2;
    }
    __threadfence();
    __syncthreads();                          // partials published
    if (tid == 0) {
        int old = atomicAdd(ctr, 1);
        int target = ((old >> 5) << 5) + 32;  // this launch's window (monotonic)
        while (*(volatile int*)ctr < target) {}
    }
    __syncthreads();
    __threadfence();

    float S = 0.f, S2 = 0.f;
#pragma unroll 8
    for (int j = 0; j < NB; j++) {
        S  += __ldcg(&partial[j * 256 + o]);
        S2 += __ldcg(&partial[j * 256 + 128 + o]);
    }
    float inv_n = 1.f / (float)n;
    float mu = S * inv_n;
    float var = S2 * inv_n - mu * mu;
    float scal = gamma[o] * rsqrtf(var + 1e-5f);
    float be = beta[o];

    // pw norm: per-warp shuffle reduction (no cross-warp sync; identical in every warp)
    float pwn;
    {
        float v = 0.f;
#pragma unroll
        for (int c = 0; c < 4; c++) {
            float p = spw[lane + c * 32];
            v = fmaf(p, p, v);
        }
#pragma unroll
        for (int st = 16; st > 0; st >>= 1)
            v += __shfl_xor_sync(0xffffffffu, v, st);
        pwn = sqrtf(v);
    }

    // BN + ReLU in place (4-way row parallel)
    for (int i = g4; i < npg; i += 4) {
        tile[i * 129 + o] = fmaxf(scal * (tile[i * 129 + o] - mu) + be, 0.f);
    }
    __syncthreads();

    // scores: tpn threads cooperate per node, shuffle-reduce
    const int tpn = POOL_NT / npg;           // 4, 8, or 16
    const int node = tid / tpn;
    const int q = tid - node * tpn;
    const int cpt = HH / tpn;                // 32, 16, or 8
    {
        float acc = 0.f;
        const float* trow = tile + node * 129 + q * cpt;
        for (int c = 0; c < cpt; c++) acc += trow[c] * spw[q * cpt + c];
        for (int st = tpn >> 1; st > 0; st >>= 1)
            acc += __shfl_xor_sync(0xffffffffu, acc, st);
        if (q == 0) sc[node] = tanhf(acc / pwn);
    }
    __syncthreads();

    // rank = count of strictly better (index tie-break), tpn-way split + shuffle
    {
        float mine = sc[node];
        int r = 0;
        for (int j = q; j < npg; j += tpn) {
            float sj = sc[j];
            r += (sj > mine) || (sj == mine && j < node);
        }
        for (int st = tpn >> 1; st > 0; st >>= 1)
            r += __shfl_xor_sync(0xffffffffu, r, st);
        if (q == 0) rankA[node] = r;
    }
    __syncthreads();

    // gather kept nodes (4-way row parallel): hout + split-A
    for (int i = g4; i < npg; i += 4) {
        int r = rankA[i];
        if (r < kk) {
            int nid = b * kk + r;
            float val = tile[i * 129 + o] * sc[i];
            hout[(size_t)nid * HH + o] = val;
            __nv_bfloat16 h1, h2b;
            split2(val, h1, h2b);
            __nv_bfloat16* row = Ab + (size_t)nid * (2 * HH) + o;
            row[0] = h1; row[HH] = h2b;
        }
    }

    // remap this graph's edges (256 edges, 512 threads)
    for (int e = b * EPG + tid; e < (b + 1) * EPG; e += POOL_NT) {
        if (valid[e]) {
            int rs = rankA[src[e] - base];
            int rd = rankA[dst[e] - base];
            if (rs < kk && rd < kk) { src[e] = b * kk + rs; dst[e] = b * kk + rd; }
            else valid[e] = 0;
        }
    }
}

// fused meanpool + 2-layer MLP + sigmoid
__global__ void readout_k(const float* __restrict__ h, const float* __restrict__ w1,
                          const float* __restrict__ b1, const float* __restrict__ w2,
                          const float* __restrict__ b2, float* __restrict__ out) {
    __shared__ float sg[HH];
    __shared__ float red[64];
    int b = blockIdx.x, o = threadIdx.x;
    float acc = 0.f;
#pragma unroll
    for (int i = 0; i < K3; i++) acc += h[(size_t)(b * K3 + i) * HH + o];
    sg[o] = acc * (1.f / K3);
    __syncthreads();
    if (o < 64) {
        float a = b1[o];
        for (int i = 0; i < HH; i++) a = fmaf(sg[i], w1[i * 64 + o], a);
        a = fmaxf(a, 0.f);
        red[o] = a * w2[o];
    }
    __syncthreads();
    for (int st = 32; st > 0; st >>= 1) {
        if (o < st) red[o] += red[o + st];
        __syncthreads();
    }
    if (o == 0) out[b] = 1.f / (1.f + expf(-(red[0] + b2[0])));
}

// ---------------- host ----------------
static inline int pool_smem(int npg) {
    return (npg * 129 + 128 + npg + 512 + 512 + npg) * 4;
}

extern "C" void kernel_launch(void* const* d_in, const int* in_sizes, int n_in,
                              void* d_out, int out_size) {
    const float* x     = (const float*)d_in[0];
    const int*   ei    = (const int*)d_in[1];
    const float* ea    = (const float*)d_in[2];
    const float* nn1_w = (const float*)d_in[4];
    const float* nn1_b = (const float*)d_in[5];
    const float* root1 = (const float*)d_in[6];
    const float* bias1 = (const float*)d_in[7];
    const float* nn2_w = (const float*)d_in[8];
    const float* nn2_b = (const float*)d_in[9];
    const float* root2 = (const float*)d_in[10];
    const float* bias2 = (const float*)d_in[11];
    const float* nn3_w = (const float*)d_in[12];
    const float* nn3_b = (const float*)d_in[13];
    const float* root3 = (const float*)d_in[14];
    const float* bias3 = (const float*)d_in[15];
    const float* gamma1 = (const float*)d_in[16];
    const float* beta1  = (const float*)d_in[17];
    const float* gamma2 = (const float*)d_in[18];
    const float* beta2  = (const float*)d_in[19];
    const float* gamma3 = (const float*)d_in[20];
    const float* beta3  = (const float*)d_in[21];
    const float* pw1 = (const float*)d_in[22];
    const float* pw2 = (const float*)d_in[23];
    const float* pw3 = (const float*)d_in[24];
    const float* l1w = (const float*)d_in[25];
    const float* l1b = (const float*)d_in[26];
    const float* l2w = (const float*)d_in[27];
    const float* l2b = (const float*)d_in[28];
    float* out = (float*)d_out;

    float *yp, *hp, *h2p, *partp;
    __nv_bfloat16 *Abp, *Bb1p, *Bb2p, *Bb3p;
    int *srcp, *dstp, *validp, *ctrp;
    cudaGetSymbolAddress((void**)&yp, g_y);
    cudaGetSymbolAddress((void**)&Abp, g_Ab);
    cudaGetSymbolAddress((void**)&Bb1p, g_Bb1);
    cudaGetSymbolAddress((void**)&Bb2p, g_Bb2);
    cudaGetSymbolAddress((void**)&Bb3p, g_Bb3);
    cudaGetSymbolAddress((void**)&hp, g_h);
    cudaGetSymbolAddress((void**)&h2p, g_h2);
    cudaGetSymbolAddress((void**)&partp, g_partial);
    cudaGetSymbolAddress((void**)&srcp, g_src);
    cudaGetSymbolAddress((void**)&dstp, g_dst);
    cudaGetSymbolAddress((void**)&validp, g_valid);
    cudaGetSymbolAddress((void**)&ctrp, g_ctr);

    cudaFuncSetAttribute(gemm_mma_k, cudaFuncAttributeMaxDynamicSharedMemorySize, GEMM_SMEM);
    cudaFuncSetAttribute(fused_pool_k, cudaFuncAttributeMaxDynamicSharedMemorySize,
                         pool_smem(NPG0));

    // ---- fused prep (edges + split_A + all split_B) ----
    prep_k<<<PREP_BLOCKS, 256>>>(ei, x, Abp,
                                 nn1_w, nn1_b, root1, Bb1p,
                                 nn2_w, nn2_b, root2, Bb2p,
                                 nn3_w, nn3_b, root3, Bb3p,
                                 srcp, dstp, validp);

    // ---- layer 1: n=4096, cin=64 ----
    gemm_mma_k<<<dim3(NDB, NN0 / 128), 256, GEMM_SMEM>>>(Abp, Bb1p, yp, bias1, h2p, CIN0);
    edge_msg_k<<<NE / 4, 128>>>(ea, yp, h2p, srcp, dstp, validp);
    fused_pool_k<<<NB, POOL_NT, pool_smem(NPG0)>>>(
        h2p, partp, ctrp + 0, gamma1, beta1, pw1, hp, Abp, srcp, dstp, validp,
        NPG0, K1, NN0);

    // ---- layer 2: n=2048, cin=128 ----
    int n2 = NB * K1;
    gemm_mma_k<<<dim3(NDB, n2 / 128), 256, GEMM_SMEM>>>(Abp, Bb2p, yp, bias2, h2p, HH);
    edge_msg_k<<<NE / 4, 128>>>(ea, yp, h2p, srcp, dstp, validp);
    fused_pool_k<<<NB, POOL_NT, pool_smem(K1)>>>(
        h2p, partp, ctrp + 1, gamma2, beta2, pw2, hp, Abp, srcp, dstp, validp,
        K1, K2, n2);

    // ---- layer 3: n=1024, cin=128 ----
    int n3 = NB * K2;
    gemm_mma_k<<<dim3(NDB, n3 / 128), 256, GEMM_SMEM>>>(Abp, Bb3p, yp, bias3, h2p, HH);
    edge_msg_k<<<NE / 4, 128>>>(ea, yp, h2p, srcp, dstp, validp);
    fused_pool_k<<<NB, POOL_NT, pool_smem(K2)>>>(
        h2p, partp, ctrp + 2, gamma3, beta3, pw3, hp, Abp, srcp, dstp, validp,
        K2, K3, n3);

    // ---- readout ----
    readout_k<<<NB, HH>>>(hp, l1w, l1b, l2w, l2b, out);
}

// round 15
// speedup vs baseline: 2.1395x; 1.0788x over previous
#include <cuda_runtime.h>
#include <cuda_bf16.h>
#include <math.h>
#include <stdint.h>

// Problem constants
#define NB   32
#define NPG0 128
#define NE   8192
#define EPG  (NE/NB)
#define CIN0 64
#define ED   32
#define HH   128
#define CED  33
#define NDB  34
#define YC   (CED*HH)     // 4224
#define K1   64
#define K2   32
#define K3   16
#define NN0  (NB*NPG0)

// ---------------- scratch ----------------
__device__ float g_y[NN0 * YC];
__device__ __nv_bfloat16 g_Ab[NN0 * 2 * HH];
__device__ __nv_bfloat16 g_Bb1[(NDB * HH) * 2 * CIN0];
__device__ __nv_bfloat16 g_Bb2[(NDB * HH) * 2 * HH];
__device__ __nv_bfloat16 g_Bb3[(NDB * HH) * 2 * HH];
__device__ float g_h2[NN0 * HH];
__device__ int   g_src[NE], g_dst[NE], g_valid[NE];
__device__ float g_partial[NB * 256];
__device__ int   g_ctr[4];

// ---------------- helpers ----------------
__device__ __forceinline__ void split2(float x, __nv_bfloat16& h1, __nv_bfloat16& h2) {
    h1 = __float2bfloat16(x);
    h2 = __float2bfloat16(x - __bfloat162float(h1));
}
__device__ __forceinline__ uint32_t smem_u32(const void* p) {
    return (uint32_t)__cvta_generic_to_shared(p);
}
__device__ __forceinline__ void cp_async16(uint32_t saddr, const void* gaddr) {
    asm volatile("cp.async.cg.shared.global [%0], [%1], 16;" :: "r"(saddr), "l"(gaddr));
}
__device__ __forceinline__ void ldsm4(uint32_t& r0, uint32_t& r1, uint32_t& r2, uint32_t& r3,
                                      uint32_t addr) {
    asm volatile("ldmatrix.sync.aligned.m8n8.x4.shared.b16 {%0,%1,%2,%3}, [%4];"
                 : "=r"(r0), "=r"(r1), "=r"(r2), "=r"(r3) : "r"(addr));
}
__device__ __forceinline__ void mma16816(float* c, const uint32_t* a, const uint32_t* b) {
    asm volatile("mma.sync.aligned.m16n8k16.row.col.f32.bf16.bf16.f32 "
                 "{%0,%1,%2,%3}, {%4,%5,%6,%7}, {%8,%9}, {%0,%1,%2,%3};"
                 : "+f"(c[0]), "+f"(c[1]), "+f"(c[2]), "+f"(c[3])
                 : "r"(a[0]), "r"(a[1]), "r"(a[2]), "r"(a[3]), "r"(b[0]), "r"(b[1]));
}

// ---------------- fused prep (unchanged from R14) ----------------
__device__ __forceinline__ void split_B_elem(const float* __restrict__ W,
                                             const float* __restrict__ bvec,
                                             const float* __restrict__ root,
                                             __nv_bfloat16* __restrict__ Bb,
                                             int i, int cin) {
    int t = i / cin, k = i - t * cin;
    int d = t >> 7, o = t & 127;
    float w;
    if (d < ED)       w = W[(size_t)(d * cin + k) * HH + o];
    else if (d == ED) w = bvec[(size_t)k * HH + o];
    else              w = root[(size_t)k * HH + o];
    __nv_bfloat16 b1, b2;
    split2(w, b1, b2);
    __nv_bfloat16* row = Bb + (size_t)t * 2 * cin + k;
    row[0] = b1; row[cin] = b2;
}

#define PREP_SEG0 32
#define PREP_SEG1 1024
#define PREP_SEG2 1088
#define PREP_SEG3 2176
#define PREP_SEG4 2176
#define PREP_BLOCKS (PREP_SEG0 + PREP_SEG1 + PREP_SEG2 + PREP_SEG3 + PREP_SEG4)

__global__ void prep_k(const int* __restrict__ ei, const float* __restrict__ x,
                       __nv_bfloat16* __restrict__ Ab,
                       const float* __restrict__ nn1_w, const float* __restrict__ nn1_b,
                       const float* __restrict__ root1, __nv_bfloat16* __restrict__ Bb1,
                       const float* __restrict__ nn2_w, const float* __restrict__ nn2_b,
                       const float* __restrict__ root2, __nv_bfloat16* __restrict__ Bb2,
                       const float* __restrict__ nn3_w, const float* __restrict__ nn3_b,
                       const float* __restrict__ root3, __nv_bfloat16* __restrict__ Bb3,
                       int* __restrict__ src, int* __restrict__ dst,
                       int* __restrict__ valid) {
    int blk = blockIdx.x;
    if (blk < PREP_SEG0) {
        int e = blk * 256 + threadIdx.x;
        src[e] = ei[e]; dst[e] = ei[NE + e]; valid[e] = 1;
        return;
    }
    blk -= PREP_SEG0;
    if (blk < PREP_SEG1) {
        int i = blk * 256 + threadIdx.x;
        int r = i >> 6, k = i & 63;
        __nv_bfloat16 h1, h2;
        split2(x[i], h1, h2);
        __nv_bfloat16* row = Ab + (size_t)r * 2 * CIN0 + k;
        row[0] = h1; row[CIN0] = h2;
        return;
    }
    blk -= PREP_SEG1;
    if (blk < PREP_SEG2) {
        split_B_elem(nn1_w, nn1_b, root1, Bb1, blk * 256 + threadIdx.x, CIN0);
        return;
    }
    blk -= PREP_SEG2;
    if (blk < PREP_SEG3) {
        split_B_elem(nn2_w, nn2_b, root2, Bb2, blk * 256 + threadIdx.x, HH);
        return;
    }
    blk -= PREP_SEG3;
    split_B_elem(nn3_w, nn3_b, root3, Bb3, blk * 256 + threadIdx.x, HH);
}

// ---------------- raw mma.sync GEMM (R11/R14 mainloop, unchanged) ----------------
#define SROW 72
#define STG  (128 * SROW)
#define GEMM_SMEM (3 * 2 * STG * 2)

__global__ __launch_bounds__(256, 2)
void gemm_mma_k(const __nv_bfloat16* __restrict__ Ab, const __nv_bfloat16* __restrict__ Bb,
                float* __restrict__ Y, const float* __restrict__ bias,
                float* __restrict__ h2agg, int cin) {
    extern __shared__ __nv_bfloat16 sm[];
    const int tid = threadIdx.x;
    const int lane = tid & 31;
    const int wid = tid >> 5;
    const int warp_m = wid & 3;
    const int warp_n = wid >> 2;
    const int mbase = blockIdx.y * 128;
    const int nbase = blockIdx.x * 128;
    const int Kp2 = 2 * cin;
    const int NPAIR = cin >> 6;
    const int NCH = NPAIR * 2;

    float acc[2][8][4];
#pragma unroll
    for (int i = 0; i < 2; i++)
#pragma unroll
        for (int j = 0; j < 8; j++)
#pragma unroll
            for (int q = 0; q < 4; q++) acc[i][j][q] = 0.f;

    auto prefetch = [&](int c) {
        const int s = c % 3;
        const int kc = (c & 1) * cin + ((c >> 1) << 6);
        __nv_bfloat16* base = sm + s * 2 * STG;
#pragma unroll
        for (int u = 0; u < 8; u++) {
            int q = tid + u * 256;
            int isB = q >> 10;
            int qq = q & 1023;
            int r = qq >> 3, ch = qq & 7;
            const __nv_bfloat16* g = isB
                ? (Bb + (size_t)(nbase + r) * Kp2 + kc + ch * 8)
                : (Ab + (size_t)(mbase + r) * Kp2 + kc + ch * 8);
            cp_async16(smem_u32(base + isB * STG + r * SROW + ch * 8), g);
        }
        asm volatile("cp.async.commit_group;" ::: "memory");
    };

    prefetch(0);
    prefetch(1);
    if (NCH > 2) prefetch(2);

    for (int p = 0; p < NPAIR; p++) {
        if (2 * p + 2 < NCH) asm volatile("cp.async.wait_group 1;" ::: "memory");
        else                 asm volatile("cp.async.wait_group 0;" ::: "memory");
        __syncthreads();

        const int sA = (2 * p) % 3, sB = (2 * p + 1) % 3;
        const uint32_t a1_base = smem_u32(sm + sA * 2 * STG);
        const uint32_t b1_base = a1_base + STG * 2;
        const uint32_t a2_base = smem_u32(sm + sB * 2 * STG);
        const uint32_t b2_base = a2_base + STG * 2;

        const int m8 = lane >> 3;
        const int arow_off = warp_m * 32 + (lane & 15);
        const int acol_sel = (lane >> 4) * 8;
        const int brow0 = warp_n * 64 + (m8 >> 1) * 8 + (lane & 7);
        const int bcol_sel = (m8 & 1) * 8;

#pragma unroll
        for (int kk = 0; kk < 4; kk++) {
            const uint32_t aoff = (uint32_t)(kk * 16 + acol_sel) * 2;
            const uint32_t boff = (uint32_t)(kk * 16 + bcol_sel) * 2;

            uint32_t af1[2][4];
#pragma unroll
            for (int i = 0; i < 2; i++)
                ldsm4(af1[i][0], af1[i][1], af1[i][2], af1[i][3],
                      a1_base + (uint32_t)((arow_off + i * 16) * SROW) * 2 + aoff);
            uint32_t bf1[8][2];
#pragma unroll
            for (int g = 0; g < 4; g++)
                ldsm4(bf1[2 * g][0], bf1[2 * g][1], bf1[2 * g + 1][0], bf1[2 * g + 1][1],
                      b1_base + (uint32_t)((brow0 + g * 16) * SROW) * 2 + boff);
#pragma unroll
            for (int i = 0; i < 2; i++)
#pragma unroll
                for (int j = 0; j < 8; j++)
                    mma16816(acc[i][j], af1[i], bf1[j]);

            uint32_t af2[2][4];
#pragma unroll
            for (int i = 0; i < 2; i++)
                ldsm4(af2[i][0], af2[i][1], af2[i][2], af2[i][3],
                      a2_base + (uint32_t)((arow_off + i * 16) * SROW) * 2 + aoff);
#pragma unroll
            for (int i = 0; i < 2; i++)
#pragma unroll
                for (int j = 0; j < 8; j++)
                    mma16816(acc[i][j], af2[i], bf1[j]);

            uint32_t bf2[8][2];
#pragma unroll
            for (int g = 0; g < 4; g++)
                ldsm4(bf2[2 * g][0], bf2[2 * g][1], bf2[2 * g + 1][0], bf2[2 * g + 1][1],
                      b2_base + (uint32_t)((brow0 + g * 16) * SROW) * 2 + boff);
#pragma unroll
            for (int i = 0; i < 2; i++)
#pragma unroll
                for (int j = 0; j < 8; j++)
                    mma16816(acc[i][j], af1[i], bf2[j]);
        }

        if (2 * p + 3 < NCH) {
            __syncthreads();
            prefetch(2 * p + 3);
        }
    }

    const int gid = lane >> 2, tig = lane & 3;
    if (blockIdx.x == 33) {
#pragma unroll
        for (int i = 0; i < 2; i++) {
            int row = mbase + warp_m * 32 + i * 16 + gid;
#pragma unroll
            for (int j = 0; j < 8; j++) {
                int col = warp_n * 64 + j * 8 + tig * 2;
                float b0 = bias[col], b1 = bias[col + 1];
                float* d0 = h2agg + (size_t)row * HH + col;
                d0[0] = acc[i][j][0] + b0;
                d0[1] = acc[i][j][1] + b1;
                float* d1 = h2agg + (size_t)(row + 8) * HH + col;
                d1[0] = acc[i][j][2] + b0;
                d1[1] = acc[i][j][3] + b1;
            }
        }
    } else {
#pragma unroll
        for (int i = 0; i < 2; i++) {
            int row = mbase + warp_m * 32 + i * 16 + gid;
#pragma unroll
            for (int j = 0; j < 8; j++) {
                int col = nbase + warp_n * 64 + j * 8 + tig * 2;
                *reinterpret_cast<float2*>(Y + (size_t)row * YC + col) =
                    make_float2(acc[i][j][0], acc[i][j][1]);
                *reinterpret_cast<float2*>(Y + (size_t)(row + 8) * YC + col) =
                    make_float2(acc[i][j][2], acc[i][j][3]);
            }
        }
    }
}

// ---------------- edge_msg (unchanged) ----------------
__global__ void edge_msg_k(const float* __restrict__ ea, const float* __restrict__ y,
                           float* __restrict__ agg, const int* __restrict__ src,
                           const int* __restrict__ dst, const int* __restrict__ valid) {
    int e = blockIdx.x * 4 + (threadIdx.x >> 5);
    int lane = threadIdx.x & 31;
    if (!valid[e]) return;
    float av = ea[(size_t)e * ED + lane];
    const float4* yr = reinterpret_cast<const float4*>(y + (size_t)src[e] * YC) + lane;
    float4 acc = make_float4(0.f, 0.f, 0.f, 0.f);
#pragma unroll
    for (int d = 0; d < ED; d++) {
        float ad = __shfl_sync(0xffffffffu, av, d);
        float4 v = yr[d * 32];
        acc.x = fmaf(ad, v.x, acc.x);
        acc.y = fmaf(ad, v.y, acc.y);
        acc.z = fmaf(ad, v.z, acc.z);
        acc.w = fmaf(ad, v.w, acc.w);
    }
    {
        float4 v = yr[ED * 32];
        acc.x += v.x; acc.y += v.y; acc.z += v.z; acc.w += v.w;
    }
    float* ag = agg + (size_t)dst[e] * HH + lane * 4;
    atomicAdd(ag + 0, acc.x);
    atomicAdd(ag + 1, acc.y);
    atomicAdd(ag + 2, acc.z);
    atomicAdd(ag + 3, acc.w);
}

// ---------------- fused pool v2: float4, 512 threads ----------------
// Thread map: quad = tid&31 (4 channels), rowg = tid>>5 (16 row groups).
// Phases: load h2 (float4) + stats -> grid barrier -> BN coef -> BN apply ->
// score (tpn coop) -> rank -> [gather split-A + remap] or [meanpool+MLP+sigmoid].
#define POOL_NT 512

__global__ __launch_bounds__(POOL_NT, 1)
void fused_pool_k(const float* __restrict__ h2, float* __restrict__ partial,
                  int* __restrict__ ctr,
                  const float* __restrict__ gamma, const float* __restrict__ beta,
                  const float* __restrict__ pw,
                  __nv_bfloat16* __restrict__ Ab,
                  int* __restrict__ src, int* __restrict__ dst,
                  int* __restrict__ valid,
                  int npg, int kk, int n, int last,
                  const float* __restrict__ w1, const float* __restrict__ b1,
                  const float* __restrict__ w2, const float* __restrict__ b2,
                  float* __restrict__ out) {
    extern __shared__ float fs[];
    float*  tile  = fs;                         // npg * 132 (33 float4/row)
    float*  spw   = tile + npg * 132;           // 128
    float*  sc    = spw + 128;                  // npg
    float*  gred  = sc + npg;                   // 2048 (16 groups x 128 ch)
    float*  gred2 = gred + 2048;                // 2048
    float*  bnsc  = gred2 + 2048;               // 128
    float*  bnbe  = bnsc + 128;                 // 128
    float*  mlp1  = bnbe + 128;                 // 64
    int*    rankA = (int*)(mlp1 + 64);          // npg

    float4* tile4  = reinterpret_cast<float4*>(tile);
    float4* gred4  = reinterpret_cast<float4*>(gred);
    float4* gred24 = reinterpret_cast<float4*>(gred2);
    const float4* spw4 = reinterpret_cast<const float4*>(spw);

    const int b = blockIdx.x;
    const int tid = threadIdx.x;
    const int lane = tid & 31;
    const int quad = tid & 31;                  // channel quad 0..31
    const int rowg = tid >> 5;                  // 0..15
    const int base = b * npg;

    // ---- load h2 (float4) + per-group stats ----
    float4 s4 = make_float4(0.f, 0.f, 0.f, 0.f);
    float4 q4 = make_float4(0.f, 0.f, 0.f, 0.f);
    for (int r = rowg; r < npg; r += 16) {
        float4 v = reinterpret_cast<const float4*>(h2)[(size_t)(base + r) * 32 + quad];
        tile4[r * 33 + quad] = v;
        s4.x += v.x; s4.y += v.y; s4.z += v.z; s4.w += v.w;
        q4.x = fmaf(v.x, v.x, q4.x); q4.y = fmaf(v.y, v.y, q4.y);
        q4.z = fmaf(v.z, v.z, q4.z); q4.w = fmaf(v.w, v.w, q4.w);
    }
    gred4[rowg * 32 + quad] = s4;
    gred24[rowg * 32 + quad] = q4;
    if (tid < 128) spw[tid] = pw[tid];
    __syncthreads();
    if (tid < 128) {
        float ss = 0.f, ss2 = 0.f;
#pragma unroll
        for (int g = 0; g < 16; g++) {
            ss  += gred[g * 128 + tid];
            ss2 += gred2[g * 128 + tid];
        }
        partial[b * 256 + tid] = ss;
        partial[b * 256 + 128 + tid] = ss2;
    }
    __threadfence();
    __syncthreads();
    if (tid == 0) {
        int old = atomicAdd(ctr, 1);
        int target = ((old >> 5) << 5) + 32;
        while (*(volatile int*)ctr < target) {}
    }
    __syncthreads();
    __threadfence();

    // ---- BN coefficients (128 threads, one per channel) ----
    if (tid < 128) {
        float S = 0.f, S2 = 0.f;
#pragma unroll 8
        for (int j = 0; j < NB; j++) {
            S  += __ldcg(&partial[j * 256 + tid]);
            S2 += __ldcg(&partial[j * 256 + 128 + tid]);
        }
        float inv_n = 1.f / (float)n;
        float mu = S * inv_n;
        float var = S2 * inv_n - mu * mu;
        float scal = gamma[tid] * rsqrtf(var + 1e-5f);
        bnsc[tid] = scal;
        bnbe[tid] = beta[tid] - scal * mu;
    }
    __syncthreads();

    // pw norm: per-warp shuffle reduction
    float pwn;
    {
        float v = 0.f;
#pragma unroll
        for (int c = 0; c < 4; c++) {
            float p = spw[lane + c * 32];
            v = fmaf(p, p, v);
        }
#pragma unroll
        for (int st = 16; st > 0; st >>= 1)
            v += __shfl_xor_sync(0xffffffffu, v, st);
        pwn = sqrtf(v);
    }

    // ---- BN + ReLU in place (float4) ----
    {
        float4 sc4 = reinterpret_cast<const float4*>(bnsc)[quad];
        float4 be4 = reinterpret_cast<const float4*>(bnbe)[quad];
        for (int r = rowg; r < npg; r += 16) {
            float4 v = tile4[r * 33 + quad];
            v.x = fmaxf(fmaf(sc4.x, v.x, be4.x), 0.f);
            v.y = fmaxf(fmaf(sc4.y, v.y, be4.y), 0.f);
            v.z = fmaxf(fmaf(sc4.z, v.z, be4.z), 0.f);
            v.w = fmaxf(fmaf(sc4.w, v.w, be4.w), 0.f);
            tile4[r * 33 + quad] = v;
        }
    }
    __syncthreads();

    // ---- scores (tpn threads per node, float4) ----
    const int tpn = POOL_NT / npg;              // 4, 8, 16
    const int node = tid / tpn;
    const int q = tid - node * tpn;
    const int q4n = (HH / tpn) >> 2;            // float4 per coop thread: 8,4,2
    {
        float acc = 0.f;
        const float4* trow = tile4 + node * 33 + q * q4n;
        const float4* wrow = spw4 + q * q4n;
#pragma unroll 4
        for (int c = 0; c < q4n; c++) {
            float4 v = trow[c], w = wrow[c];
            acc = fmaf(v.x, w.x, acc); acc = fmaf(v.y, w.y, acc);
            acc = fmaf(v.z, w.z, acc); acc = fmaf(v.w, w.w, acc);
        }
        for (int st = tpn >> 1; st > 0; st >>= 1)
            acc += __shfl_xor_sync(0xffffffffu, acc, st);
        if (q == 0) sc[node] = tanhf(acc / pwn);
    }
    __syncthreads();

    // ---- rank ----
    {
        float mine = sc[node];
        int r = 0;
        for (int j = q; j < npg; j += tpn) {
            float sj = sc[j];
            r += (sj > mine) || (sj == mine && j < node);
        }
        for (int st = tpn >> 1; st > 0; st >>= 1)
            r += __shfl_xor_sync(0xffffffffu, r, st);
        if (q == 0) rankA[node] = r;
    }
    __syncthreads();

    if (!last) {
        // gather kept nodes -> split-A (next GEMM input); no hout (dead)
        for (int r = rowg; r < npg; r += 16) {
            int rk = rankA[r];
            if (rk < kk) {
                int nid = b * kk + rk;
                float scv = sc[r];
                float4 v = tile4[r * 33 + quad];
                v.x *= scv; v.y *= scv; v.z *= scv; v.w *= scv;
                __nv_bfloat16 a1[4], a2[4];
                split2(v.x, a1[0], a2[0]); split2(v.y, a1[1], a2[1]);
                split2(v.z, a1[2], a2[2]); split2(v.w, a1[3], a2[3]);
                __nv_bfloat16* row = Ab + (size_t)nid * 256;
                *reinterpret_cast<uint2*>(row + quad * 4) =
                    *reinterpret_cast<uint2*>(a1);
                *reinterpret_cast<uint2*>(row + 128 + quad * 4) =
                    *reinterpret_cast<uint2*>(a2);
            }
        }
        // remap edges
        for (int e = b * EPG + tid; e < (b + 1) * EPG; e += POOL_NT) {
            if (valid[e]) {
                int rs = rankA[src[e] - base];
                int rd = rankA[dst[e] - base];
                if (rs < kk && rd < kk) { src[e] = b * kk + rs; dst[e] = b * kk + rd; }
                else valid[e] = 0;
            }
        }
    } else {
        // ---- fused readout: mean over kept + MLP + sigmoid ----
        float4 m4 = make_float4(0.f, 0.f, 0.f, 0.f);
        for (int r = rowg; r < npg; r += 16) {
            int rk = rankA[r];
            if (rk < kk) {
                float scv = sc[r];
                float4 v = tile4[r * 33 + quad];
                m4.x = fmaf(v.x, scv, m4.x); m4.y = fmaf(v.y, scv, m4.y);
                m4.z = fmaf(v.z, scv, m4.z); m4.w = fmaf(v.w, scv, m4.w);
            }
        }
        gred4[rowg * 32 + quad] = m4;
        __syncthreads();
        if (tid < 128) {
            float m = 0.f;
#pragma unroll
            for (int g = 0; g < 16; g++) m += gred[g * 128 + tid];
            spw[tid] = m * (1.f / (float)kk);   // reuse spw as mean buffer
        }
        __syncthreads();
        // MLP layer 1: 64 outputs x 8 threads
        int j = tid >> 3, q8 = tid & 7;
        float a = 0.f;
        for (int c = q8; c < HH; c += 8) a = fmaf(spw[c], w1[c * 64 + j], a);
#pragma unroll
        for (int st = 4; st > 0; st >>= 1)
            a += __shfl_xor_sync(0xffffffffu, a, st);
        if (q8 == 0) mlp1[j] = fmaxf(a + b1[j], 0.f) * w2[j];
        __syncthreads();
        if (tid < 32) {
            float v = mlp1[tid] + mlp1[tid + 32];
#pragma unroll
            for (int st = 16; st > 0; st >>= 1)
                v += __shfl_xor_sync(0xffffffffu, v, st);
            if (tid == 0) out[b] = 1.f / (1.f + expf(-(v + b2[0])));
        }
    }
}

// ---------------- host ----------------
static inline int pool_smem(int npg) {
    return (npg * 132 + 128 + npg + 2048 + 2048 + 128 + 128 + 64 + npg) * 4;
}

extern "C" void kernel_launch(void* const* d_in, const int* in_sizes, int n_in,
                              void* d_out, int out_size) {
    const float* x     = (const float*)d_in[0];
    const int*   ei    = (const int*)d_in[1];
    const float* ea    = (const float*)d_in[2];
    const float* nn1_w = (const float*)d_in[4];
    const float* nn1_b = (const float*)d_in[5];
    const float* root1 = (const float*)d_in[6];
    const float* bias1 = (const float*)d_in[7];
    const float* nn2_w = (const float*)d_in[8];
    const float* nn2_b = (const float*)d_in[9];
    const float* root2 = (const float*)d_in[10];
    const float* bias2 = (const float*)d_in[11];
    const float* nn3_w = (const float*)d_in[12];
    const float* nn3_b = (const float*)d_in[13];
    const float* root3 = (const float*)d_in[14];
    const float* bias3 = (const float*)d_in[15];
    const float* gamma1 = (const float*)d_in[16];
    const float* beta1  = (const float*)d_in[17];
    const float* gamma2 = (const float*)d_in[18];
    const float* beta2  = (const float*)d_in[19];
    const float* gamma3 = (const float*)d_in[20];
    const float* beta3  = (const float*)d_in[21];
    const float* pw1 = (const float*)d_in[22];
    const float* pw2 = (const float*)d_in[23];
    const float* pw3 = (const float*)d_in[24];
    const float* l1w = (const float*)d_in[25];
    const float* l1b = (const float*)d_in[26];
    const float* l2w = (const float*)d_in[27];
    const float* l2b = (const float*)d_in[28];
    float* out = (float*)d_out;

    float *yp, *h2p, *partp;
    __nv_bfloat16 *Abp, *Bb1p, *Bb2p, *Bb3p;
    int *srcp, *dstp, *validp, *ctrp;
    cudaGetSymbolAddress((void**)&yp, g_y);
    cudaGetSymbolAddress((void**)&Abp, g_Ab);
    cudaGetSymbolAddress((void**)&Bb1p, g_Bb1);
    cudaGetSymbolAddress((void**)&Bb2p, g_Bb2);
    cudaGetSymbolAddress((void**)&Bb3p, g_Bb3);
    cudaGetSymbolAddress((void**)&h2p, g_h2);
    cudaGetSymbolAddress((void**)&partp, g_partial);
    cudaGetSymbolAddress((void**)&srcp, g_src);
    cudaGetSymbolAddress((void**)&dstp, g_dst);
    cudaGetSymbolAddress((void**)&validp, g_valid);
    cudaGetSymbolAddress((void**)&ctrp, g_ctr);

    cudaFuncSetAttribute(gemm_mma_k, cudaFuncAttributeMaxDynamicSharedMemorySize, GEMM_SMEM);
    cudaFuncSetAttribute(fused_pool_k, cudaFuncAttributeMaxDynamicSharedMemorySize,
                         pool_smem(NPG0));

    prep_k<<<PREP_BLOCKS, 256>>>(ei, x, Abp,
                                 nn1_w, nn1_b, root1, Bb1p,
                                 nn2_w, nn2_b, root2, Bb2p,
                                 nn3_w, nn3_b, root3, Bb3p,
                                 srcp, dstp, validp);

    // ---- layer 1 ----
    gemm_mma_k<<<dim3(NDB, NN0 / 128), 256, GEMM_SMEM>>>(Abp, Bb1p, yp, bias1, h2p, CIN0);
    edge_msg_k<<<NE / 4, 128>>>(ea, yp, h2p, srcp, dstp, validp);
    fused_pool_k<<<NB, POOL_NT, pool_smem(NPG0)>>>(
        h2p, partp, ctrp + 0, gamma1, beta1, pw1, Abp, srcp, dstp, validp,
        NPG0, K1, NN0, 0, nullptr, nullptr, nullptr, nullptr, nullptr);

    // ---- layer 2 ----
    int n2 = NB * K1;
    gemm_mma_k<<<dim3(NDB, n2 / 128), 256, GEMM_SMEM>>>(Abp, Bb2p, yp, bias2, h2p, HH);
    edge_msg_k<<<NE / 4, 128>>>(ea, yp, h2p, srcp, dstp, validp);
    fused_pool_k<<<NB, POOL_NT, pool_smem(K1)>>>(
        h2p, partp, ctrp + 1, gamma2, beta2, pw2, Abp, srcp, dstp, validp,
        K1, K2, n2, 0, nullptr, nullptr, nullptr, nullptr, nullptr);

    // ---- layer 3 + fused readout ----
    int n3 = NB * K2;
    gemm_mma_k<<<dim3(NDB, n3 / 128), 256, GEMM_SMEM>>>(Abp, Bb3p, yp, bias3, h2p, HH);
    edge_msg_k<<<NE / 4, 128>>>(ea, yp, h2p, srcp, dstp, validp);
    fused_pool_k<<<NB, POOL_NT, pool_smem(K2)>>>(
        h2p, partp, ctrp + 2, gamma3, beta3, pw3, Abp, srcp, dstp, validp,
        K2, K3, n3, 1, l1w, l1b, l2w, l2b, out);
}

// round 16
// speedup vs baseline: 2.1401x; 1.0002x over previous
#include <cuda_runtime.h>
#include <cuda_bf16.h>
#include <math.h>
#include <stdint.h>

// Problem constants
#define NB   32
#define NPG0 128
#define NE   8192
#define EPG  (NE/NB)
#define CIN0 64
#define ED   32
#define HH   128
#define CED  33
#define NDB  34
#define YC   (CED*HH)     // 4224
#define K1   64
#define K2   32
#define K3   16
#define NN0  (NB*NPG0)

// ---------------- scratch ----------------
__device__ float g_y[NN0 * YC];
__device__ __nv_bfloat16 g_Ab[NN0 * 2 * HH];
__device__ __nv_bfloat16 g_Bb1[(NDB * HH) * 2 * CIN0];
__device__ __nv_bfloat16 g_Bb2[(NDB * HH) * 2 * HH];
__device__ __nv_bfloat16 g_Bb3[(NDB * HH) * 2 * HH];
__device__ float g_h2[NN0 * HH];
__device__ int   g_src[NE], g_dst[NE], g_valid[NE];
__device__ float g_partial[NB * 256];
__device__ int   g_ctr[4];

// ---------------- helpers ----------------
__device__ __forceinline__ void split2(float x, __nv_bfloat16& h1, __nv_bfloat16& h2) {
    h1 = __float2bfloat16(x);
    h2 = __float2bfloat16(x - __bfloat162float(h1));
}
__device__ __forceinline__ uint32_t smem_u32(const void* p) {
    return (uint32_t)__cvta_generic_to_shared(p);
}
__device__ __forceinline__ void cp_async16(uint32_t saddr, const void* gaddr) {
    asm volatile("cp.async.cg.shared.global [%0], [%1], 16;" :: "r"(saddr), "l"(gaddr));
}
__device__ __forceinline__ void ldsm4(uint32_t& r0, uint32_t& r1, uint32_t& r2, uint32_t& r3,
                                      uint32_t addr) {
    asm volatile("ldmatrix.sync.aligned.m8n8.x4.shared.b16 {%0,%1,%2,%3}, [%4];"
                 : "=r"(r0), "=r"(r1), "=r"(r2), "=r"(r3) : "r"(addr));
}
__device__ __forceinline__ void mma16816(float* c, const uint32_t* a, const uint32_t* b) {
    asm volatile("mma.sync.aligned.m16n8k16.row.col.f32.bf16.bf16.f32 "
                 "{%0,%1,%2,%3}, {%4,%5,%6,%7}, {%8,%9}, {%0,%1,%2,%3};"
                 : "+f"(c[0]), "+f"(c[1]), "+f"(c[2]), "+f"(c[3])
                 : "r"(a[0]), "r"(a[1]), "r"(a[2]), "r"(a[3]), "r"(b[0]), "r"(b[1]));
}

// ---------------- fused prep (unchanged) ----------------
__device__ __forceinline__ void split_B_elem(const float* __restrict__ W,
                                             const float* __restrict__ bvec,
                                             const float* __restrict__ root,
                                             __nv_bfloat16* __restrict__ Bb,
                                             int i, int cin) {
    int t = i / cin, k = i - t * cin;
    int d = t >> 7, o = t & 127;
    float w;
    if (d < ED)       w = W[(size_t)(d * cin + k) * HH + o];
    else if (d == ED) w = bvec[(size_t)k * HH + o];
    else              w = root[(size_t)k * HH + o];
    __nv_bfloat16 b1, b2;
    split2(w, b1, b2);
    __nv_bfloat16* row = Bb + (size_t)t * 2 * cin + k;
    row[0] = b1; row[cin] = b2;
}

#define PREP_SEG0 32
#define PREP_SEG1 1024
#define PREP_SEG2 1088
#define PREP_SEG3 2176
#define PREP_SEG4 2176
#define PREP_BLOCKS (PREP_SEG0 + PREP_SEG1 + PREP_SEG2 + PREP_SEG3 + PREP_SEG4)

__global__ void prep_k(const int* __restrict__ ei, const float* __restrict__ x,
                       __nv_bfloat16* __restrict__ Ab,
                       const float* __restrict__ nn1_w, const float* __restrict__ nn1_b,
                       const float* __restrict__ root1, __nv_bfloat16* __restrict__ Bb1,
                       const float* __restrict__ nn2_w, const float* __restrict__ nn2_b,
                       const float* __restrict__ root2, __nv_bfloat16* __restrict__ Bb2,
                       const float* __restrict__ nn3_w, const float* __restrict__ nn3_b,
                       const float* __restrict__ root3, __nv_bfloat16* __restrict__ Bb3,
                       int* __restrict__ src, int* __restrict__ dst,
                       int* __restrict__ valid) {
    int blk = blockIdx.x;
    if (blk < PREP_SEG0) {
        int e = blk * 256 + threadIdx.x;
        src[e] = ei[e]; dst[e] = ei[NE + e]; valid[e] = 1;
        return;
    }
    blk -= PREP_SEG0;
    if (blk < PREP_SEG1) {
        int i = blk * 256 + threadIdx.x;
        int r = i >> 6, k = i & 63;
        __nv_bfloat16 h1, h2;
        split2(x[i], h1, h2);
        __nv_bfloat16* row = Ab + (size_t)r * 2 * CIN0 + k;
        row[0] = h1; row[CIN0] = h2;
        return;
    }
    blk -= PREP_SEG1;
    if (blk < PREP_SEG2) {
        split_B_elem(nn1_w, nn1_b, root1, Bb1, blk * 256 + threadIdx.x, CIN0);
        return;
    }
    blk -= PREP_SEG2;
    if (blk < PREP_SEG3) {
        split_B_elem(nn2_w, nn2_b, root2, Bb2, blk * 256 + threadIdx.x, HH);
        return;
    }
    blk -= PREP_SEG3;
    split_B_elem(nn3_w, nn3_b, root3, Bb3, blk * 256 + threadIdx.x, HH);
}

// ---------------- raw mma.sync GEMM (unchanged) ----------------
#define SROW 72
#define STG  (128 * SROW)
#define GEMM_SMEM (3 * 2 * STG * 2)

__global__ __launch_bounds__(256, 2)
void gemm_mma_k(const __nv_bfloat16* __restrict__ Ab, const __nv_bfloat16* __restrict__ Bb,
                float* __restrict__ Y, const float* __restrict__ bias,
                float* __restrict__ h2agg, int cin) {
    extern __shared__ __nv_bfloat16 sm[];
    const int tid = threadIdx.x;
    const int lane = tid & 31;
    const int wid = tid >> 5;
    const int warp_m = wid & 3;
    const int warp_n = wid >> 2;
    const int mbase = blockIdx.y * 128;
    const int nbase = blockIdx.x * 128;
    const int Kp2 = 2 * cin;
    const int NPAIR = cin >> 6;
    const int NCH = NPAIR * 2;

    float acc[2][8][4];
#pragma unroll
    for (int i = 0; i < 2; i++)
#pragma unroll
        for (int j = 0; j < 8; j++)
#pragma unroll
            for (int q = 0; q < 4; q++) acc[i][j][q] = 0.f;

    auto prefetch = [&](int c) {
        const int s = c % 3;
        const int kc = (c & 1) * cin + ((c >> 1) << 6);
        __nv_bfloat16* base = sm + s * 2 * STG;
#pragma unroll
        for (int u = 0; u < 8; u++) {
            int q = tid + u * 256;
            int isB = q >> 10;
            int qq = q & 1023;
            int r = qq >> 3, ch = qq & 7;
            const __nv_bfloat16* g = isB
                ? (Bb + (size_t)(nbase + r) * Kp2 + kc + ch * 8)
                : (Ab + (size_t)(mbase + r) * Kp2 + kc + ch * 8);
            cp_async16(smem_u32(base + isB * STG + r * SROW + ch * 8), g);
        }
        asm volatile("cp.async.commit_group;" ::: "memory");
    };

    prefetch(0);
    prefetch(1);
    if (NCH > 2) prefetch(2);

    for (int p = 0; p < NPAIR; p++) {
        if (2 * p + 2 < NCH) asm volatile("cp.async.wait_group 1;" ::: "memory");
        else                 asm volatile("cp.async.wait_group 0;" ::: "memory");
        __syncthreads();

        const int sA = (2 * p) % 3, sB = (2 * p + 1) % 3;
        const uint32_t a1_base = smem_u32(sm + sA * 2 * STG);
        const uint32_t b1_base = a1_base + STG * 2;
        const uint32_t a2_base = smem_u32(sm + sB * 2 * STG);
        const uint32_t b2_base = a2_base + STG * 2;

        const int m8 = lane >> 3;
        const int arow_off = warp_m * 32 + (lane & 15);
        const int acol_sel = (lane >> 4) * 8;
        const int brow0 = warp_n * 64 + (m8 >> 1) * 8 + (lane & 7);
        const int bcol_sel = (m8 & 1) * 8;

#pragma unroll
        for (int kk = 0; kk < 4; kk++) {
            const uint32_t aoff = (uint32_t)(kk * 16 + acol_sel) * 2;
            const uint32_t boff = (uint32_t)(kk * 16 + bcol_sel) * 2;

            uint32_t af1[2][4];
#pragma unroll
            for (int i = 0; i < 2; i++)
                ldsm4(af1[i][0], af1[i][1], af1[i][2], af1[i][3],
                      a1_base + (uint32_t)((arow_off + i * 16) * SROW) * 2 + aoff);
            uint32_t bf1[8][2];
#pragma unroll
            for (int g = 0; g < 4; g++)
                ldsm4(bf1[2 * g][0], bf1[2 * g][1], bf1[2 * g + 1][0], bf1[2 * g + 1][1],
                      b1_base + (uint32_t)((brow0 + g * 16) * SROW) * 2 + boff);
#pragma unroll
            for (int i = 0; i < 2; i++)
#pragma unroll
                for (int j = 0; j < 8; j++)
                    mma16816(acc[i][j], af1[i], bf1[j]);

            uint32_t af2[2][4];
#pragma unroll
            for (int i = 0; i < 2; i++)
                ldsm4(af2[i][0], af2[i][1], af2[i][2], af2[i][3],
                      a2_base + (uint32_t)((arow_off + i * 16) * SROW) * 2 + aoff);
#pragma unroll
            for (int i = 0; i < 2; i++)
#pragma unroll
                for (int j = 0; j < 8; j++)
                    mma16816(acc[i][j], af2[i], bf1[j]);

            uint32_t bf2[8][2];
#pragma unroll
            for (int g = 0; g < 4; g++)
                ldsm4(bf2[2 * g][0], bf2[2 * g][1], bf2[2 * g + 1][0], bf2[2 * g + 1][1],
                      b2_base + (uint32_t)((brow0 + g * 16) * SROW) * 2 + boff);
#pragma unroll
            for (int i = 0; i < 2; i++)
#pragma unroll
                for (int j = 0; j < 8; j++)
                    mma16816(acc[i][j], af1[i], bf2[j]);
        }

        if (2 * p + 3 < NCH) {
            __syncthreads();
            prefetch(2 * p + 3);
        }
    }

    const int gid = lane >> 2, tig = lane & 3;
    if (blockIdx.x == 33) {
#pragma unroll
        for (int i = 0; i < 2; i++) {
            int row = mbase + warp_m * 32 + i * 16 + gid;
#pragma unroll
            for (int j = 0; j < 8; j++) {
                int col = warp_n * 64 + j * 8 + tig * 2;
                float b0 = bias[col], b1 = bias[col + 1];
                float* d0 = h2agg + (size_t)row * HH + col;
                d0[0] = acc[i][j][0] + b0;
                d0[1] = acc[i][j][1] + b1;
                float* d1 = h2agg + (size_t)(row + 8) * HH + col;
                d1[0] = acc[i][j][2] + b0;
                d1[1] = acc[i][j][3] + b1;
            }
        }
    } else {
#pragma unroll
        for (int i = 0; i < 2; i++) {
            int row = mbase + warp_m * 32 + i * 16 + gid;
#pragma unroll
            for (int j = 0; j < 8; j++) {
                int col = nbase + warp_n * 64 + j * 8 + tig * 2;
                *reinterpret_cast<float2*>(Y + (size_t)row * YC + col) =
                    make_float2(acc[i][j][0], acc[i][j][1]);
                *reinterpret_cast<float2*>(Y + (size_t)(row + 8) * YC + col) =
                    make_float2(acc[i][j][2], acc[i][j][3]);
            }
        }
    }
}

// ---------------- edge_msg (unchanged) ----------------
__global__ void edge_msg_k(const float* __restrict__ ea, const float* __restrict__ y,
                           float* __restrict__ agg, const int* __restrict__ src,
                           const int* __restrict__ dst, const int* __restrict__ valid) {
    int e = blockIdx.x * 4 + (threadIdx.x >> 5);
    int lane = threadIdx.x & 31;
    if (!valid[e]) return;
    float av = ea[(size_t)e * ED + lane];
    const float4* yr = reinterpret_cast<const float4*>(y + (size_t)src[e] * YC) + lane;
    float4 acc = make_float4(0.f, 0.f, 0.f, 0.f);
#pragma unroll
    for (int d = 0; d < ED; d++) {
        float ad = __shfl_sync(0xffffffffu, av, d);
        float4 v = yr[d * 32];
        acc.x = fmaf(ad, v.x, acc.x);
        acc.y = fmaf(ad, v.y, acc.y);
        acc.z = fmaf(ad, v.z, acc.z);
        acc.w = fmaf(ad, v.w, acc.w);
    }
    {
        float4 v = yr[ED * 32];
        acc.x += v.x; acc.y += v.y; acc.z += v.z; acc.w += v.w;
    }
    float* ag = agg + (size_t)dst[e] * HH + lane * 4;
    atomicAdd(ag + 0, acc.x);
    atomicAdd(ag + 1, acc.y);
    atomicAdd(ag + 2, acc.z);
    atomicAdd(ag + 3, acc.w);
}

// ---------------- fused pool v3 ----------------
#define POOL_NT 512

__global__ __launch_bounds__(POOL_NT, 1)
void fused_pool_k(const float* __restrict__ h2, float* __restrict__ partial,
                  int* __restrict__ ctr,
                  const float* __restrict__ gamma, const float* __restrict__ beta,
                  const float* __restrict__ pw,
                  __nv_bfloat16* __restrict__ Ab,
                  int* __restrict__ src, int* __restrict__ dst,
                  int* __restrict__ valid,
                  int npg, int kk, int n, int last,
                  const float* __restrict__ w1, const float* __restrict__ b1,
                  const float* __restrict__ w2, const float* __restrict__ b2,
                  float* __restrict__ out) {
    extern __shared__ float fs[];
    float*  tile  = fs;                         // npg * 132
    float*  spw   = tile + npg * 132;           // 128
    float*  sc    = spw + 128;                  // npg
    float*  gred  = sc + npg;                   // 2048
    float*  gred2 = gred + 2048;                // 2048
    float*  bnsc  = gred2 + 2048;               // 128
    float*  bnbe  = bnsc + 128;                 // 128
    float*  mlp1  = bnbe + 128;                 // 64
    int*    rankA = (int*)(mlp1 + 64);          // npg

    float4* tile4  = reinterpret_cast<float4*>(tile);
    float4* gred4  = reinterpret_cast<float4*>(gred);
    float4* gred24 = reinterpret_cast<float4*>(gred2);
    const float4* spw4 = reinterpret_cast<const float4*>(spw);

    const int b = blockIdx.x;
    const int tid = threadIdx.x;
    const int lane = tid & 31;
    const int quad = tid & 31;
    const int rowg = tid >> 5;
    const int base = b * npg;

    // ---- load h2 (float4) + per-group stats ----
    float4 s4 = make_float4(0.f, 0.f, 0.f, 0.f);
    float4 q4 = make_float4(0.f, 0.f, 0.f, 0.f);
    for (int r = rowg; r < npg; r += 16) {
        float4 v = reinterpret_cast<const float4*>(h2)[(size_t)(base + r) * 32 + quad];
        tile4[r * 33 + quad] = v;
        s4.x += v.x; s4.y += v.y; s4.z += v.z; s4.w += v.w;
        q4.x = fmaf(v.x, v.x, q4.x); q4.y = fmaf(v.y, v.y, q4.y);
        q4.z = fmaf(v.z, v.z, q4.z); q4.w = fmaf(v.w, v.w, q4.w);
    }
    gred4[rowg * 32 + quad] = s4;
    gred24[rowg * 32 + quad] = q4;
    if (tid < 128) spw[tid] = pw[tid];
    __syncthreads();
    if (tid < 128) {
        float ss = 0.f, ss2 = 0.f;
#pragma unroll
        for (int g = 0; g < 16; g++) {
            ss  += gred[g * 128 + tid];
            ss2 += gred2[g * 128 + tid];
        }
        partial[b * 256 + tid] = ss;
        partial[b * 256 + 128 + tid] = ss2;
    }
    __threadfence();
    __syncthreads();
    if (tid == 0) {
        int old = atomicAdd(ctr, 1);
        int target = ((old >> 5) << 5) + 32;
        while (*(volatile int*)ctr < target) __nanosleep(32);
    }
    __syncthreads();
    __threadfence();

    // ---- BN partial reduction: 4 groups x 8 graphs each (parallel L2 loads) ----
    {
        int g = tid >> 7;               // 0..3
        int o128 = tid & 127;
        float S = 0.f, S2 = 0.f;
#pragma unroll
        for (int j = g * 8; j < g * 8 + 8; j++) {
            S  += __ldcg(&partial[j * 256 + o128]);
            S2 += __ldcg(&partial[j * 256 + 128 + o128]);
        }
        gred[g * 128 + o128] = S;
        gred2[g * 128 + o128] = S2;
    }
    __syncthreads();
    if (tid < 128) {
        float S  = gred[tid] + gred[128 + tid] + gred[256 + tid] + gred[384 + tid];
        float S2 = gred2[tid] + gred2[128 + tid] + gred2[256 + tid] + gred2[384 + tid];
        float inv_n = 1.f / (float)n;
        float mu = S * inv_n;
        float var = S2 * inv_n - mu * mu;
        float scal = gamma[tid] * rsqrtf(var + 1e-5f);
        bnsc[tid] = scal;
        bnbe[tid] = beta[tid] - scal * mu;
    }
    __syncthreads();

    // pw norm: per-warp shuffle reduction
    float pwn;
    {
        float v = 0.f;
#pragma unroll
        for (int c = 0; c < 4; c++) {
            float p = spw[lane + c * 32];
            v = fmaf(p, p, v);
        }
#pragma unroll
        for (int st = 16; st > 0; st >>= 1)
            v += __shfl_xor_sync(0xffffffffu, v, st);
        pwn = sqrtf(v);
    }

    // ---- BN + ReLU in place (float4) ----
    {
        float4 sc4 = reinterpret_cast<const float4*>(bnsc)[quad];
        float4 be4 = reinterpret_cast<const float4*>(bnbe)[quad];
        for (int r = rowg; r < npg; r += 16) {
            float4 v = tile4[r * 33 + quad];
            v.x = fmaxf(fmaf(sc4.x, v.x, be4.x), 0.f);
            v.y = fmaxf(fmaf(sc4.y, v.y, be4.y), 0.f);
            v.z = fmaxf(fmaf(sc4.z, v.z, be4.z), 0.f);
            v.w = fmaxf(fmaf(sc4.w, v.w, be4.w), 0.f);
            tile4[r * 33 + quad] = v;
        }
    }
    __syncthreads();

    // ---- scores ----
    const int tpn = POOL_NT / npg;
    const int node = tid / tpn;
    const int q = tid - node * tpn;
    const int q4n = (HH / tpn) >> 2;
    {
        float acc = 0.f;
        const float4* trow = tile4 + node * 33 + q * q4n;
        const float4* wrow = spw4 + q * q4n;
#pragma unroll 4
        for (int c = 0; c < q4n; c++) {
            float4 v = trow[c], w = wrow[c];
            acc = fmaf(v.x, w.x, acc); acc = fmaf(v.y, w.y, acc);
            acc = fmaf(v.z, w.z, acc); acc = fmaf(v.w, w.w, acc);
        }
        for (int st = tpn >> 1; st > 0; st >>= 1)
            acc += __shfl_xor_sync(0xffffffffu, acc, st);
        if (q == 0) sc[node] = tanhf(acc / pwn);
    }
    __syncthreads();

    // ---- rank ----
    {
        float mine = sc[node];
        int r = 0;
        for (int j = q; j < npg; j += tpn) {
            float sj = sc[j];
            r += (sj > mine) || (sj == mine && j < node);
        }
        for (int st = tpn >> 1; st > 0; st >>= 1)
            r += __shfl_xor_sync(0xffffffffu, r, st);
        if (q == 0) rankA[node] = r;
    }
    __syncthreads();

    if (!last) {
        for (int r = rowg; r < npg; r += 16) {
            int rk = rankA[r];
            if (rk < kk) {
                int nid = b * kk + rk;
                float scv = sc[r];
                float4 v = tile4[r * 33 + quad];
                v.x *= scv; v.y *= scv; v.z *= scv; v.w *= scv;
                __nv_bfloat16 a1[4], a2[4];
                split2(v.x, a1[0], a2[0]); split2(v.y, a1[1], a2[1]);
                split2(v.z, a1[2], a2[2]); split2(v.w, a1[3], a2[3]);
                __nv_bfloat16* row = Ab + (size_t)nid * 256;
                *reinterpret_cast<uint2*>(row + quad * 4) =
                    *reinterpret_cast<uint2*>(a1);
                *reinterpret_cast<uint2*>(row + 128 + quad * 4) =
                    *reinterpret_cast<uint2*>(a2);
            }
        }
        for (int e = b * EPG + tid; e < (b + 1) * EPG; e += POOL_NT) {
            if (valid[e]) {
                int rs = rankA[src[e] - base];
                int rd = rankA[dst[e] - base];
                if (rs < kk && rd < kk) { src[e] = b * kk + rs; dst[e] = b * kk + rd; }
                else valid[e] = 0;
            }
        }
    } else {
        float4 m4 = make_float4(0.f, 0.f, 0.f, 0.f);
        for (int r = rowg; r < npg; r += 16) {
            int rk = rankA[r];
            if (rk < kk) {
                float scv = sc[r];
                float4 v = tile4[r * 33 + quad];
                m4.x = fmaf(v.x, scv, m4.x); m4.y = fmaf(v.y, scv, m4.y);
                m4.z = fmaf(v.z, scv, m4.z); m4.w = fmaf(v.w, scv, m4.w);
            }
        }
        gred4[rowg * 32 + quad] = m4;
        __syncthreads();
        if (tid < 128) {
            float m = 0.f;
#pragma unroll
            for (int g = 0; g < 16; g++) m += gred[g * 128 + tid];
            spw[tid] = m * (1.f / (float)kk);
        }
        __syncthreads();
        int j = tid >> 3, q8 = tid & 7;
        float a = 0.f;
        for (int c = q8; c < HH; c += 8) a = fmaf(spw[c], w1[c * 64 + j], a);
#pragma unroll
        for (int st = 4; st > 0; st >>= 1)
            a += __shfl_xor_sync(0xffffffffu, a, st);
        if (q8 == 0) mlp1[j] = fmaxf(a + b1[j], 0.f) * w2[j];
        __syncthreads();
        if (tid < 32) {
            float v = mlp1[tid] + mlp1[tid + 32];
#pragma unroll
            for (int st = 16; st > 0; st >>= 1)
                v += __shfl_xor_sync(0xffffffffu, v, st);
            if (tid == 0) out[b] = 1.f / (1.f + expf(-(v + b2[0])));
        }
    }
}

// ---------------- host ----------------
static inline int pool_smem(int npg) {
    return (npg * 132 + 128 + npg + 2048 + 2048 + 128 + 128 + 64 + npg) * 4;
}

extern "C" void kernel_launch(void* const* d_in, const int* in_sizes, int n_in,
                              void* d_out, int out_size) {
    const float* x     = (const float*)d_in[0];
    const int*   ei    = (const int*)d_in[1];
    const float* ea    = (const float*)d_in[2];
    const float* nn1_w = (const float*)d_in[4];
    const float* nn1_b = (const float*)d_in[5];
    const float* root1 = (const float*)d_in[6];
    const float* bias1 = (const float*)d_in[7];
    const float* nn2_w = (const float*)d_in[8];
    const float* nn2_b = (const float*)d_in[9];
    const float* root2 = (const float*)d_in[10];
    const float* bias2 = (const float*)d_in[11];
    const float* nn3_w = (const float*)d_in[12];
    const float* nn3_b = (const float*)d_in[13];
    const float* root3 = (const float*)d_in[14];
    const float* bias3 = (const float*)d_in[15];
    const float* gamma1 = (const float*)d_in[16];
    const float* beta1  = (const float*)d_in[17];
    const float* gamma2 = (const float*)d_in[18];
    const float* beta2  = (const float*)d_in[19];
    const float* gamma3 = (const float*)d_in[20];
    const float* beta3  = (const float*)d_in[21];
    const float* pw1 = (const float*)d_in[22];
    const float* pw2 = (const float*)d_in[23];
    const float* pw3 = (const float*)d_in[24];
    const float* l1w = (const float*)d_in[25];
    const float* l1b = (const float*)d_in[26];
    const float* l2w = (const float*)d_in[27];
    const float* l2b = (const float*)d_in[28];
    float* out = (float*)d_out;

    float *yp, *h2p, *partp;
    __nv_bfloat16 *Abp, *Bb1p, *Bb2p, *Bb3p;
    int *srcp, *dstp, *validp, *ctrp;
    cudaGetSymbolAddress((void**)&yp, g_y);
    cudaGetSymbolAddress((void**)&Abp, g_Ab);
    cudaGetSymbolAddress((void**)&Bb1p, g_Bb1);
    cudaGetSymbolAddress((void**)&Bb2p, g_Bb2);
    cudaGetSymbolAddress((void**)&Bb3p, g_Bb3);
    cudaGetSymbolAddress((void**)&h2p, g_h2);
    cudaGetSymbolAddress((void**)&partp, g_partial);
    cudaGetSymbolAddress((void**)&srcp, g_src);
    cudaGetSymbolAddress((void**)&dstp, g_dst);
    cudaGetSymbolAddress((void**)&validp, g_valid);
    cudaGetSymbolAddress((void**)&ctrp, g_ctr);

    cudaFuncSetAttribute(gemm_mma_k, cudaFuncAttributeMaxDynamicSharedMemorySize, GEMM_SMEM);
    cudaFuncSetAttribute(fused_pool_k, cudaFuncAttributeMaxDynamicSharedMemorySize,
                         pool_smem(NPG0));

    prep_k<<<PREP_BLOCKS, 256>>>(ei, x, Abp,
                                 nn1_w, nn1_b, root1, Bb1p,
                                 nn2_w, nn2_b, root2, Bb2p,
                                 nn3_w, nn3_b, root3, Bb3p,
                                 srcp, dstp, validp);

    // ---- layer 1 ----
    gemm_mma_k<<<dim3(NDB, NN0 / 128), 256, GEMM_SMEM>>>(Abp, Bb1p, yp, bias1, h2p, CIN0);
    edge_msg_k<<<NE / 4, 128>>>(ea, yp, h2p, srcp, dstp, validp);
    fused_pool_k<<<NB, POOL_NT, pool_smem(NPG0)>>>(
        h2p, partp, ctrp + 0, gamma1, beta1, pw1, Abp, srcp, dstp, validp,
        NPG0, K1, NN0, 0, nullptr, nullptr, nullptr, nullptr, nullptr);

    // ---- layer 2 ----
    int n2 = NB * K1;
    gemm_mma_k<<<dim3(NDB, n2 / 128), 256, GEMM_SMEM>>>(Abp, Bb2p, yp, bias2, h2p, HH);
    edge_msg_k<<<NE / 4, 128>>>(ea, yp, h2p, srcp, dstp, validp);
    fused_pool_k<<<NB, POOL_NT, pool_smem(K1)>>>(
        h2p, partp, ctrp + 1, gamma2, beta2, pw2, Abp, srcp, dstp, validp,
        K1, K2, n2, 0, nullptr, nullptr, nullptr, nullptr, nullptr);

    // ---- layer 3 + fused readout ----
    int n3 = NB * K2;
    gemm_mma_k<<<dim3(NDB, n3 / 128), 256, GEMM_SMEM>>>(Abp, Bb3p, yp, bias3, h2p, HH);
    edge_msg_k<<<NE / 4, 128>>>(ea, yp, h2p, srcp, dstp, validp);
    fused_pool_k<<<NB, POOL_NT, pool_smem(K2)>>>(
        h2p, partp, ctrp + 2, gamma3, beta3, pw3, Abp, srcp, dstp, validp,
        K2, K3, n3, 1, l1w, l1b, l2w, l2b, out);
}